// round 1
// baseline (speedup 1.0000x reference)
#include <cuda_runtime.h>
#include <math.h>

// Problem constants
#define HDIM 512
#define NHEAD 8
#define HEADD 64
#define BATCH 8
#define SEQL 1024
#define MTOT (BATCH * SEQL)  // 8192

// Scratch: 16 units of [8192 x 512] floats = 268 MB
__device__ float g_scratch[(size_t)16 * 8192 * 512];

// ---------------------------------------------------------------------------
// Generic SGEMM (NT): C[m,n] = sum_k scaleA*(A1[m,k]+A2[m,k]) * W[n,k] + bias[n]
// A row-major [M x K] with row stride lda; W row-major [N x K] (weights [out,in]).
// Grid: (N/64, M/64), block 256. All dims multiples of 64 (K mult of 16).
// ---------------------------------------------------------------------------
__global__ void sgemm_nt(const float* __restrict__ A1, const float* __restrict__ A2,
                         float scaleA, int lda,
                         const float* __restrict__ W, const float* __restrict__ bias,
                         float* __restrict__ C, int ldc, int K)
{
    __shared__ float As[16][64];  // As[k][m]
    __shared__ float Ws[16][64];  // Ws[k][n]

    const int bm = blockIdx.y * 64;
    const int bn = blockIdx.x * 64;
    const int tid = threadIdx.x;
    const int ty = tid >> 4;      // 0..15
    const int tx = tid & 15;      // 0..15
    const int lrow = tid >> 2;    // 0..63
    const int lq = tid & 3;       // 0..3

    float acc[4][4] = {};

    for (int k0 = 0; k0 < K; k0 += 16) {
        // Load A tile (64 rows x 16 k), transposed into As[k][m]
        {
            const float* p = A1 + (size_t)(bm + lrow) * lda + k0 + lq * 4;
            float4 v = *(const float4*)p;
            if (A2) {
                float4 v2 = *(const float4*)(A2 + (size_t)(bm + lrow) * lda + k0 + lq * 4);
                v.x += v2.x; v.y += v2.y; v.z += v2.z; v.w += v2.w;
            }
            As[lq * 4 + 0][lrow] = v.x * scaleA;
            As[lq * 4 + 1][lrow] = v.y * scaleA;
            As[lq * 4 + 2][lrow] = v.z * scaleA;
            As[lq * 4 + 3][lrow] = v.w * scaleA;
        }
        // Load W tile (64 n-rows x 16 k), transposed into Ws[k][n]
        {
            const float4 v = *(const float4*)(W + (size_t)(bn + lrow) * K + k0 + lq * 4);
            Ws[lq * 4 + 0][lrow] = v.x;
            Ws[lq * 4 + 1][lrow] = v.y;
            Ws[lq * 4 + 2][lrow] = v.z;
            Ws[lq * 4 + 3][lrow] = v.w;
        }
        __syncthreads();

        #pragma unroll
        for (int k = 0; k < 16; k++) {
            float4 av = *(const float4*)&As[k][ty * 4];
            float4 wv = *(const float4*)&Ws[k][tx * 4];
            float a[4] = {av.x, av.y, av.z, av.w};
            float w[4] = {wv.x, wv.y, wv.z, wv.w};
            #pragma unroll
            for (int i = 0; i < 4; i++)
                #pragma unroll
                for (int j = 0; j < 4; j++)
                    acc[i][j] = fmaf(a[i], w[j], acc[i][j]);
        }
        __syncthreads();
    }

    #pragma unroll
    for (int i = 0; i < 4; i++) {
        float4 o;
        o.x = acc[i][0] + bias[bn + tx * 4 + 0];
        o.y = acc[i][1] + bias[bn + tx * 4 + 1];
        o.z = acc[i][2] + bias[bn + tx * 4 + 2];
        o.w = acc[i][3] + bias[bn + tx * 4 + 3];
        *(float4*)(C + (size_t)(bm + ty * 4 + i) * ldc + bn + tx * 4) = o;
    }
}

// ---------------------------------------------------------------------------
// FP32 flash attention, HD=64, BQ=BK=64.
// Q/K/V are [B*L, *] buffers with row strides sq/skv (floats); head h occupies
// columns [h*64, h*64+64). O written to [B*L, so] at head columns.
// Grid: (L/64, NH, B). Block: 256 threads (16x16, each owns 4x4).
// Shared = exactly 48 KB: QT (Q transposed) + KP (K transposed, then P) + Vs.
// ---------------------------------------------------------------------------
__global__ void flash64(const float* __restrict__ Q, const float* __restrict__ K,
                        const float* __restrict__ V, float* __restrict__ O,
                        int sq, int skv, int so)
{
    __shared__ float QT[64 * 64];  // QT[k*64 + r], pre-scaled by 1/sqrt(64)
    __shared__ float KP[64 * 64];  // phase A: KT[k*64 + c]; phase B: P[r*64 + c]
    __shared__ float Vs[64 * 64];  // Vs[c*64 + d]

    const int q0 = blockIdx.x * 64;
    const int h  = blockIdx.y;
    const int b  = blockIdx.z;
    const int tid = threadIdx.x;
    const int ty = tid >> 4;
    const int tx = tid & 15;
    const int lrow = tid >> 2;  // 0..63
    const int lq = tid & 3;     // 0..3

    const float* Qb = Q + (size_t)b * SEQL * sq  + (size_t)h * HEADD;
    const float* Kb = K + (size_t)b * SEQL * skv + (size_t)h * HEADD;
    const float* Vb = V + (size_t)b * SEQL * skv + (size_t)h * HEADD;
    float*       Ob = O + (size_t)b * SEQL * so  + (size_t)h * HEADD;

    // Load Q tile (scaled), store transposed: QT[k][r]
    #pragma unroll
    for (int u = 0; u < 4; u++) {
        const int c = (lq + 4 * u) * 4;
        float4 v = *(const float4*)(Qb + (size_t)(q0 + lrow) * sq + c);
        const float sc = 0.125f;  // 1/sqrt(64)
        QT[(c + 0) * 64 + lrow] = v.x * sc;
        QT[(c + 1) * 64 + lrow] = v.y * sc;
        QT[(c + 2) * 64 + lrow] = v.z * sc;
        QT[(c + 3) * 64 + lrow] = v.w * sc;
    }

    float o[4][4] = {};
    float mi[4] = {-INFINITY, -INFINITY, -INFINITY, -INFINITY};
    float li[4] = {};

    for (int kt = 0; kt < SEQL; kt += 64) {
        // Load K transposed and V row-major
        #pragma unroll
        for (int u = 0; u < 4; u++) {
            const int c = (lq + 4 * u) * 4;
            float4 kv = *(const float4*)(Kb + (size_t)(kt + lrow) * skv + c);
            KP[(c + 0) * 64 + lrow] = kv.x;
            KP[(c + 1) * 64 + lrow] = kv.y;
            KP[(c + 2) * 64 + lrow] = kv.z;
            KP[(c + 3) * 64 + lrow] = kv.w;
            float4 vv = *(const float4*)(Vb + (size_t)(kt + lrow) * skv + c);
            *(float4*)&Vs[lrow * 64 + c] = vv;
        }
        __syncthreads();

        // S = (Q*sc) @ K^T : each thread 4x4
        float s[4][4] = {};
        #pragma unroll 8
        for (int k = 0; k < 64; k++) {
            float4 av = *(const float4*)&QT[k * 64 + ty * 4];
            float4 bv = *(const float4*)&KP[k * 64 + tx * 4];
            float a[4] = {av.x, av.y, av.z, av.w};
            float bb[4] = {bv.x, bv.y, bv.z, bv.w};
            #pragma unroll
            for (int i = 0; i < 4; i++)
                #pragma unroll
                for (int j = 0; j < 4; j++)
                    s[i][j] = fmaf(a[i], bb[j], s[i][j]);
        }

        // Online softmax (row groups share 16 lanes; shuffle width 16)
        #pragma unroll
        for (int i = 0; i < 4; i++) {
            float mx = fmaxf(fmaxf(s[i][0], s[i][1]), fmaxf(s[i][2], s[i][3]));
            #pragma unroll
            for (int off = 8; off; off >>= 1)
                mx = fmaxf(mx, __shfl_xor_sync(0xffffffffu, mx, off, 16));
            float mnew = fmaxf(mi[i], mx);
            float corr = __expf(mi[i] - mnew);
            mi[i] = mnew;
            float rs = 0.f;
            #pragma unroll
            for (int j = 0; j < 4; j++) {
                s[i][j] = __expf(s[i][j] - mnew);
                rs += s[i][j];
            }
            #pragma unroll
            for (int off = 8; off; off >>= 1)
                rs += __shfl_xor_sync(0xffffffffu, rs, off, 16);
            li[i] = li[i] * corr + rs;
            #pragma unroll
            for (int j = 0; j < 4; j++) o[i][j] *= corr;
        }

        __syncthreads();  // everyone done reading KT
        // Write P into KP (row-major P[r][c])
        #pragma unroll
        for (int i = 0; i < 4; i++)
            #pragma unroll
            for (int j = 0; j < 4; j++)
                KP[(ty * 4 + i) * 64 + tx * 4 + j] = s[i][j];
        __syncthreads();

        // O += P @ V
        #pragma unroll 8
        for (int c = 0; c < 64; c++) {
            float p0 = KP[(ty * 4 + 0) * 64 + c];
            float p1 = KP[(ty * 4 + 1) * 64 + c];
            float p2 = KP[(ty * 4 + 2) * 64 + c];
            float p3 = KP[(ty * 4 + 3) * 64 + c];
            float4 vv = *(const float4*)&Vs[c * 64 + tx * 4];
            o[0][0] = fmaf(p0, vv.x, o[0][0]); o[0][1] = fmaf(p0, vv.y, o[0][1]);
            o[0][2] = fmaf(p0, vv.z, o[0][2]); o[0][3] = fmaf(p0, vv.w, o[0][3]);
            o[1][0] = fmaf(p1, vv.x, o[1][0]); o[1][1] = fmaf(p1, vv.y, o[1][1]);
            o[1][2] = fmaf(p1, vv.z, o[1][2]); o[1][3] = fmaf(p1, vv.w, o[1][3]);
            o[2][0] = fmaf(p2, vv.x, o[2][0]); o[2][1] = fmaf(p2, vv.y, o[2][1]);
            o[2][2] = fmaf(p2, vv.z, o[2][2]); o[2][3] = fmaf(p2, vv.w, o[2][3]);
            o[3][0] = fmaf(p3, vv.x, o[3][0]); o[3][1] = fmaf(p3, vv.y, o[3][1]);
            o[3][2] = fmaf(p3, vv.z, o[3][2]); o[3][3] = fmaf(p3, vv.w, o[3][3]);
        }
        __syncthreads();  // done with KP/Vs before next tile load
    }

    // Epilogue: O / l
    #pragma unroll
    for (int i = 0; i < 4; i++) {
        float inv = 1.0f / li[i];
        float4 ov;
        ov.x = o[i][0] * inv; ov.y = o[i][1] * inv;
        ov.z = o[i][2] * inv; ov.w = o[i][3] * inv;
        *(float4*)(Ob + (size_t)(q0 + ty * 4 + i) * so + tx * 4) = ov;
    }
}

// ---------------------------------------------------------------------------
extern "C" void kernel_launch(void* const* d_in, const int* in_sizes, int n_in,
                              void* d_out, int out_size)
{
    (void)in_sizes; (void)n_in; (void)out_size;

    const float* hs        = (const float*)d_in[0];
    const float* txt       = (const float*)d_in[1];
    const float* w_q_img   = (const float*)d_in[2];
    const float* b_q_img   = (const float*)d_in[3];
    const float* w_k_img   = (const float*)d_in[4];
    const float* b_k_img   = (const float*)d_in[5];
    const float* w_v_img   = (const float*)d_in[6];
    const float* b_v_img   = (const float*)d_in[7];
    const float* w_q_txt   = (const float*)d_in[8];
    const float* b_q_txt   = (const float*)d_in[9];
    const float* w_k_txt   = (const float*)d_in[10];
    const float* b_k_txt   = (const float*)d_in[11];
    const float* w_v_txt   = (const float*)d_in[12];
    const float* b_v_txt   = (const float*)d_in[13];
    const float* w_out_img = (const float*)d_in[14];
    const float* b_out_img = (const float*)d_in[15];
    const float* w_out_txt = (const float*)d_in[16];
    const float* b_out_txt = (const float*)d_in[17];
    const float* w_cat     = (const float*)d_in[18];
    const float* b_cat     = (const float*)d_in[19];
    const float* in_proj_w = (const float*)d_in[20];
    const float* in_proj_b = (const float*)d_in[21];
    const float* out_proj_w= (const float*)d_in[22];
    const float* out_proj_b= (const float*)d_in[23];
    float* out = (float*)d_out;

    constexpr size_t U = (size_t)MTOT * HDIM;  // 8192*512
    float* g;
    cudaGetSymbolAddress((void**)&g, g_scratch);
    float* Q0 = g + 0 * U;
    float* K0 = g + 1 * U;
    float* V0 = g + 2 * U;
    float* Q1 = g + 3 * U;
    float* K1 = g + 4 * U;
    float* V1 = g + 5 * U;
    float* C0 = g + 6 * U;
    float* C1 = g + 7 * U;
    float* C2 = g + 8 * U;
    float* C3 = g + 9 * U;
    float* OUTCAT = g + 10 * U;  // [8192 x 1024]
    float* OUTB   = g + 12 * U;  // [8192 x 512]
    float* QKV    = g + 13 * U;  // [8192 x 1536]

    const dim3 blk(256);
    const dim3 g512(HDIM / 64, MTOT / 64);      // N=512
    const dim3 g1536(3 * HDIM / 64, MTOT / 64); // N=1536
    const dim3 fg(SEQL / 64, NHEAD, BATCH);

    // 1) QKV projections
    sgemm_nt<<<g512, blk>>>(hs,  nullptr, 1.f, HDIM, w_q_img, b_q_img, Q0, HDIM, HDIM);
    sgemm_nt<<<g512, blk>>>(hs,  nullptr, 1.f, HDIM, w_k_img, b_k_img, K0, HDIM, HDIM);
    sgemm_nt<<<g512, blk>>>(hs,  nullptr, 1.f, HDIM, w_v_img, b_v_img, V0, HDIM, HDIM);
    sgemm_nt<<<g512, blk>>>(txt, nullptr, 1.f, HDIM, w_q_txt, b_q_txt, Q1, HDIM, HDIM);
    sgemm_nt<<<g512, blk>>>(txt, nullptr, 1.f, HDIM, w_k_txt, b_k_txt, K1, HDIM, HDIM);
    sgemm_nt<<<g512, blk>>>(txt, nullptr, 1.f, HDIM, w_v_txt, b_v_txt, V1, HDIM, HDIM);

    // 2) Four attentions
    flash64<<<fg, blk>>>(Q0, K0, V0, C0, HDIM, HDIM, HDIM);  // img-img
    flash64<<<fg, blk>>>(Q1, K1, V1, C1, HDIM, HDIM, HDIM);  // txt-txt
    flash64<<<fg, blk>>>(Q0, K1, V1, C2, HDIM, HDIM, HDIM);  // img-txt
    flash64<<<fg, blk>>>(Q1, K0, V0, C3, HDIM, HDIM, HDIM);  // txt-img

    // 3) out_img / out_txt with fused (a+b)*0.5, written into concat halves
    sgemm_nt<<<g512, blk>>>(C0, C2, 0.5f, HDIM, w_out_img, b_out_img, OUTCAT,       2 * HDIM, HDIM);
    sgemm_nt<<<g512, blk>>>(C1, C3, 0.5f, HDIM, w_out_txt, b_out_txt, OUTCAT + HDIM, 2 * HDIM, HDIM);

    // 4) cat linear: [8192,1024] @ w_cat^T -> [8192,512]
    sgemm_nt<<<g512, blk>>>(OUTCAT, nullptr, 1.f, 2 * HDIM, w_cat, b_cat, OUTB, HDIM, 2 * HDIM);

    // 5) pooling in_proj -> QKV [8192,1536]
    sgemm_nt<<<g1536, blk>>>(OUTB, nullptr, 1.f, HDIM, in_proj_w, in_proj_b, QKV, 3 * HDIM, HDIM);

    // 6) pooling self-attention (strided views of QKV)
    flash64<<<fg, blk>>>(QKV, QKV + HDIM, QKV + 2 * HDIM, C0, 3 * HDIM, 3 * HDIM, HDIM);

    // 7) out_proj -> final output
    sgemm_nt<<<g512, blk>>>(C0, nullptr, 1.f, HDIM, out_proj_w, out_proj_b, out, HDIM, HDIM);
}

// round 2
// speedup vs baseline: 1.9436x; 1.9436x over previous
#include <cuda_runtime.h>
#include <math.h>
#include <stdint.h>

// Problem constants
#define HDIM 512
#define NHEAD 8
#define HEADD 64
#define BATCH 8
#define SEQL 1024
#define MTOT (BATCH * SEQL)  // 8192

// Scratch: 16 units of [8192 x 512] floats = 268 MB
__device__ float g_scratch[(size_t)16 * 8192 * 512];

// fp32 -> tf32 (round to nearest) in-place bit pattern
__device__ __forceinline__ float f2tf32(float x) {
    float y;
    asm("cvt.rna.tf32.f32 %0, %1;" : "=f"(y) : "f"(x));
    return y;
}

// m16n8k8 TF32 HMMA, fp32 accumulate (D += A*B)
__device__ __forceinline__ void mma_tf32(float& d0, float& d1, float& d2, float& d3,
                                         uint32_t a0, uint32_t a1, uint32_t a2, uint32_t a3,
                                         uint32_t b0, uint32_t b1)
{
    asm volatile(
        "mma.sync.aligned.m16n8k8.row.col.f32.tf32.tf32.f32 "
        "{%0,%1,%2,%3}, {%4,%5,%6,%7}, {%8,%9}, {%0,%1,%2,%3};"
        : "+f"(d0), "+f"(d1), "+f"(d2), "+f"(d3)
        : "r"(a0), "r"(a1), "r"(a2), "r"(a3), "r"(b0), "r"(b1));
}

// ---------------------------------------------------------------------------
// TF32 GEMM (NT): C[m,n] = sum_k scaleA*(A1[m,k]+A2[m,k]) * W[n,k] + bias[n]
// CTA tile 128x128, BK=32, 256 threads (8 warps, 2x4; warp tile 64x32).
// Grid: (N/128, M/128).
// ---------------------------------------------------------------------------
#define GPAD 36
__global__ __launch_bounds__(256, 2)
void gemm_tf32(const float* __restrict__ A1, const float* __restrict__ A2,
               float scaleA, int lda,
               const float* __restrict__ W, const float* __restrict__ bias,
               float* __restrict__ C, int ldc, int K)
{
    __shared__ float As[128][GPAD];
    __shared__ float Ws[128][GPAD];

    const int bm = blockIdx.y * 128;
    const int bn = blockIdx.x * 128;
    const int tid = threadIdx.x;
    const int warp = tid >> 5;
    const int lane = tid & 31;
    const int g = lane >> 2;   // 0..7
    const int t = lane & 3;    // 0..3
    const int wm = warp >> 2;  // 0..1 -> 64 rows
    const int wn = warp & 3;   // 0..3 -> 32 cols

    const int lrow = tid >> 1;          // 0..127
    const int lcb  = (tid & 1) * 16;    // 0 or 16

    float acc[4][4][4] = {};

    for (int k0 = 0; k0 < K; k0 += 32) {
        // Stage A tile [128 x 32]
        {
            const float* p = A1 + (size_t)(bm + lrow) * lda + k0 + lcb;
            #pragma unroll
            for (int u = 0; u < 4; u++) {
                float4 v = *(const float4*)(p + 4 * u);
                if (A2) {
                    float4 v2 = *(const float4*)(A2 + (size_t)(bm + lrow) * lda + k0 + lcb + 4 * u);
                    v.x += v2.x; v.y += v2.y; v.z += v2.z; v.w += v2.w;
                }
                As[lrow][lcb + 4 * u + 0] = f2tf32(v.x * scaleA);
                As[lrow][lcb + 4 * u + 1] = f2tf32(v.y * scaleA);
                As[lrow][lcb + 4 * u + 2] = f2tf32(v.z * scaleA);
                As[lrow][lcb + 4 * u + 3] = f2tf32(v.w * scaleA);
            }
        }
        // Stage W tile [128 n x 32 k]
        {
            const float* p = W + (size_t)(bn + lrow) * K + k0 + lcb;
            #pragma unroll
            for (int u = 0; u < 4; u++) {
                float4 v = *(const float4*)(p + 4 * u);
                Ws[lrow][lcb + 4 * u + 0] = f2tf32(v.x);
                Ws[lrow][lcb + 4 * u + 1] = f2tf32(v.y);
                Ws[lrow][lcb + 4 * u + 2] = f2tf32(v.z);
                Ws[lrow][lcb + 4 * u + 3] = f2tf32(v.w);
            }
        }
        __syncthreads();

        #pragma unroll
        for (int kk = 0; kk < 4; kk++) {
            const int k = kk * 8;
            uint32_t a[4][4];
            #pragma unroll
            for (int mt = 0; mt < 4; mt++) {
                const int r = wm * 64 + mt * 16 + g;
                a[mt][0] = __float_as_uint(As[r][k + t]);
                a[mt][1] = __float_as_uint(As[r + 8][k + t]);
                a[mt][2] = __float_as_uint(As[r][k + t + 4]);
                a[mt][3] = __float_as_uint(As[r + 8][k + t + 4]);
            }
            #pragma unroll
            for (int nt = 0; nt < 4; nt++) {
                const int n = wn * 32 + nt * 8 + g;
                uint32_t b0 = __float_as_uint(Ws[n][k + t]);
                uint32_t b1 = __float_as_uint(Ws[n][k + t + 4]);
                #pragma unroll
                for (int mt = 0; mt < 4; mt++)
                    mma_tf32(acc[mt][nt][0], acc[mt][nt][1], acc[mt][nt][2], acc[mt][nt][3],
                             a[mt][0], a[mt][1], a[mt][2], a[mt][3], b0, b1);
            }
        }
        __syncthreads();
    }

    // Epilogue: bias + store
    #pragma unroll
    for (int mt = 0; mt < 4; mt++) {
        const int r = bm + wm * 64 + mt * 16 + g;
        #pragma unroll
        for (int nt = 0; nt < 4; nt++) {
            const int col = bn + wn * 32 + nt * 8 + 2 * t;
            const float bx = bias[col], by = bias[col + 1];
            float2 v0 = make_float2(acc[mt][nt][0] + bx, acc[mt][nt][1] + by);
            float2 v1 = make_float2(acc[mt][nt][2] + bx, acc[mt][nt][3] + by);
            *(float2*)(C + (size_t)r * ldc + col) = v0;
            *(float2*)(C + (size_t)(r + 8) * ldc + col) = v1;
        }
    }
}

// ---------------------------------------------------------------------------
// TF32-MMA flash attention, HD=64, BQ=BK=64, 4 warps (128 threads).
// Q/K/V: [B*L, *] with row strides sq/skv; head h at columns [h*64, h*64+64).
// Grid: (L/64, NH, B). Dynamic smem: Qs,Ks,Vs,Ps each [64][72] floats = 72KB.
// ---------------------------------------------------------------------------
#define FPAD 72
__global__ __launch_bounds__(128, 3)
void flash64_mma(const float* __restrict__ Q, const float* __restrict__ K,
                 const float* __restrict__ V, float* __restrict__ O,
                 int sq, int skv, int so)
{
    extern __shared__ float sm[];
    float* Qs = sm;                    // [64][72]
    float* Ks = Qs + 64 * FPAD;
    float* Vs = Ks + 64 * FPAD;
    float* Ps = Vs + 64 * FPAD;

    const int q0 = blockIdx.x * 64;
    const int h  = blockIdx.y;
    const int b  = blockIdx.z;
    const int tid = threadIdx.x;
    const int w = tid >> 5;       // warp 0..3, owns q rows [16w,16w+16)
    const int lane = tid & 31;
    const int g = lane >> 2;
    const int t = lane & 3;

    const float* Qb = Q + (size_t)b * SEQL * sq  + (size_t)h * HEADD;
    const float* Kb = K + (size_t)b * SEQL * skv + (size_t)h * HEADD;
    const float* Vb = V + (size_t)b * SEQL * skv + (size_t)h * HEADD;
    float*       Ob = O + (size_t)b * SEQL * so  + (size_t)h * HEADD;

    const int lrow = tid >> 1;        // 0..63
    const int lcb  = (tid & 1) * 32;  // 0 or 32

    // Load Q tile, scaled by 1/8, tf32-rounded
    {
        const float* p = Qb + (size_t)(q0 + lrow) * sq + lcb;
        #pragma unroll
        for (int u = 0; u < 8; u++) {
            float4 v = *(const float4*)(p + 4 * u);
            Qs[lrow * FPAD + lcb + 4 * u + 0] = f2tf32(v.x * 0.125f);
            Qs[lrow * FPAD + lcb + 4 * u + 1] = f2tf32(v.y * 0.125f);
            Qs[lrow * FPAD + lcb + 4 * u + 2] = f2tf32(v.z * 0.125f);
            Qs[lrow * FPAD + lcb + 4 * u + 3] = f2tf32(v.w * 0.125f);
        }
    }

    float oacc[8][4] = {};
    float mi0 = -INFINITY, mi1 = -INFINITY;
    float li0 = 0.f, li1 = 0.f;

    for (int kt = 0; kt < SEQL; kt += 64) {
        // Stage K, V tiles
        {
            const float* pk = Kb + (size_t)(kt + lrow) * skv + lcb;
            const float* pv = Vb + (size_t)(kt + lrow) * skv + lcb;
            #pragma unroll
            for (int u = 0; u < 8; u++) {
                float4 kv = *(const float4*)(pk + 4 * u);
                Ks[lrow * FPAD + lcb + 4 * u + 0] = f2tf32(kv.x);
                Ks[lrow * FPAD + lcb + 4 * u + 1] = f2tf32(kv.y);
                Ks[lrow * FPAD + lcb + 4 * u + 2] = f2tf32(kv.z);
                Ks[lrow * FPAD + lcb + 4 * u + 3] = f2tf32(kv.w);
                float4 vv = *(const float4*)(pv + 4 * u);
                Vs[lrow * FPAD + lcb + 4 * u + 0] = f2tf32(vv.x);
                Vs[lrow * FPAD + lcb + 4 * u + 1] = f2tf32(vv.y);
                Vs[lrow * FPAD + lcb + 4 * u + 2] = f2tf32(vv.z);
                Vs[lrow * FPAD + lcb + 4 * u + 3] = f2tf32(vv.w);
            }
        }
        __syncthreads();

        // S = (Q/8) @ K^T : warp computes rows [16w,16w+16) x 64 cols
        float sacc[8][4] = {};
        #pragma unroll
        for (int k8 = 0; k8 < 8; k8++) {
            const int k = k8 * 8;
            const int r = w * 16 + g;
            uint32_t a0 = __float_as_uint(Qs[r * FPAD + k + t]);
            uint32_t a1 = __float_as_uint(Qs[(r + 8) * FPAD + k + t]);
            uint32_t a2 = __float_as_uint(Qs[r * FPAD + k + t + 4]);
            uint32_t a3 = __float_as_uint(Qs[(r + 8) * FPAD + k + t + 4]);
            #pragma unroll
            for (int nt = 0; nt < 8; nt++) {
                const int n = nt * 8 + g;
                uint32_t b0 = __float_as_uint(Ks[n * FPAD + k + t]);
                uint32_t b1 = __float_as_uint(Ks[n * FPAD + k + t + 4]);
                mma_tf32(sacc[nt][0], sacc[nt][1], sacc[nt][2], sacc[nt][3],
                         a0, a1, a2, a3, b0, b1);
            }
        }

        // Online softmax. Row g: sacc[*][0..1]; row g+8: sacc[*][2..3].
        {
            float mx0 = -INFINITY, mx1 = -INFINITY;
            #pragma unroll
            for (int nt = 0; nt < 8; nt++) {
                mx0 = fmaxf(mx0, fmaxf(sacc[nt][0], sacc[nt][1]));
                mx1 = fmaxf(mx1, fmaxf(sacc[nt][2], sacc[nt][3]));
            }
            mx0 = fmaxf(mx0, __shfl_xor_sync(0xffffffffu, mx0, 1, 4));
            mx0 = fmaxf(mx0, __shfl_xor_sync(0xffffffffu, mx0, 2, 4));
            mx1 = fmaxf(mx1, __shfl_xor_sync(0xffffffffu, mx1, 1, 4));
            mx1 = fmaxf(mx1, __shfl_xor_sync(0xffffffffu, mx1, 2, 4));
            float mn0 = fmaxf(mi0, mx0);
            float mn1 = fmaxf(mi1, mx1);
            float c0 = __expf(mi0 - mn0);
            float c1 = __expf(mi1 - mn1);
            mi0 = mn0; mi1 = mn1;
            float rs0 = 0.f, rs1 = 0.f;
            #pragma unroll
            for (int nt = 0; nt < 8; nt++) {
                sacc[nt][0] = __expf(sacc[nt][0] - mn0);
                sacc[nt][1] = __expf(sacc[nt][1] - mn0);
                sacc[nt][2] = __expf(sacc[nt][2] - mn1);
                sacc[nt][3] = __expf(sacc[nt][3] - mn1);
                rs0 += sacc[nt][0] + sacc[nt][1];
                rs1 += sacc[nt][2] + sacc[nt][3];
            }
            rs0 += __shfl_xor_sync(0xffffffffu, rs0, 1, 4);
            rs0 += __shfl_xor_sync(0xffffffffu, rs0, 2, 4);
            rs1 += __shfl_xor_sync(0xffffffffu, rs1, 1, 4);
            rs1 += __shfl_xor_sync(0xffffffffu, rs1, 2, 4);
            li0 = li0 * c0 + rs0;
            li1 = li1 * c1 + rs1;
            #pragma unroll
            for (int nt = 0; nt < 8; nt++) {
                oacc[nt][0] *= c0; oacc[nt][1] *= c0;
                oacc[nt][2] *= c1; oacc[nt][3] *= c1;
            }
        }

        // Write P (warp-private rows) into Ps, fragment-layout source for A
        {
            const int r = w * 16 + g;
            #pragma unroll
            for (int nt = 0; nt < 8; nt++) {
                *(float2*)&Ps[r * FPAD + nt * 8 + 2 * t]       = make_float2(sacc[nt][0], sacc[nt][1]);
                *(float2*)&Ps[(r + 8) * FPAD + nt * 8 + 2 * t] = make_float2(sacc[nt][2], sacc[nt][3]);
            }
        }
        __syncwarp();

        // O += P @ V
        #pragma unroll
        for (int k8 = 0; k8 < 8; k8++) {
            const int k = k8 * 8;
            const int r = w * 16 + g;
            uint32_t a0 = __float_as_uint(Ps[r * FPAD + k + t]);
            uint32_t a1 = __float_as_uint(Ps[(r + 8) * FPAD + k + t]);
            uint32_t a2 = __float_as_uint(Ps[r * FPAD + k + t + 4]);
            uint32_t a3 = __float_as_uint(Ps[(r + 8) * FPAD + k + t + 4]);
            #pragma unroll
            for (int nt = 0; nt < 8; nt++) {
                uint32_t b0 = __float_as_uint(Vs[(k + t) * FPAD + nt * 8 + g]);
                uint32_t b1 = __float_as_uint(Vs[(k + t + 4) * FPAD + nt * 8 + g]);
                mma_tf32(oacc[nt][0], oacc[nt][1], oacc[nt][2], oacc[nt][3],
                         a0, a1, a2, a3, b0, b1);
            }
        }
        __syncthreads();
    }

    // Epilogue: O / l
    {
        const float inv0 = 1.0f / li0;
        const float inv1 = 1.0f / li1;
        const int r0 = q0 + w * 16 + g;
        #pragma unroll
        for (int nt = 0; nt < 8; nt++) {
            const int col = nt * 8 + 2 * t;
            *(float2*)(Ob + (size_t)r0 * so + col) =
                make_float2(oacc[nt][0] * inv0, oacc[nt][1] * inv0);
            *(float2*)(Ob + (size_t)(r0 + 8) * so + col) =
                make_float2(oacc[nt][2] * inv1, oacc[nt][3] * inv1);
        }
    }
}

// ---------------------------------------------------------------------------
extern "C" void kernel_launch(void* const* d_in, const int* in_sizes, int n_in,
                              void* d_out, int out_size)
{
    (void)in_sizes; (void)n_in; (void)out_size;

    const float* hs        = (const float*)d_in[0];
    const float* txt       = (const float*)d_in[1];
    const float* w_q_img   = (const float*)d_in[2];
    const float* b_q_img   = (const float*)d_in[3];
    const float* w_k_img   = (const float*)d_in[4];
    const float* b_k_img   = (const float*)d_in[5];
    const float* w_v_img   = (const float*)d_in[6];
    const float* b_v_img   = (const float*)d_in[7];
    const float* w_q_txt   = (const float*)d_in[8];
    const float* b_q_txt   = (const float*)d_in[9];
    const float* w_k_txt   = (const float*)d_in[10];
    const float* b_k_txt   = (const float*)d_in[11];
    const float* w_v_txt   = (const float*)d_in[12];
    const float* b_v_txt   = (const float*)d_in[13];
    const float* w_out_img = (const float*)d_in[14];
    const float* b_out_img = (const float*)d_in[15];
    const float* w_out_txt = (const float*)d_in[16];
    const float* b_out_txt = (const float*)d_in[17];
    const float* w_cat     = (const float*)d_in[18];
    const float* b_cat     = (const float*)d_in[19];
    const float* in_proj_w = (const float*)d_in[20];
    const float* in_proj_b = (const float*)d_in[21];
    const float* out_proj_w= (const float*)d_in[22];
    const float* out_proj_b= (const float*)d_in[23];
    float* out = (float*)d_out;

    constexpr size_t U = (size_t)MTOT * HDIM;  // 8192*512
    float* g;
    cudaGetSymbolAddress((void**)&g, g_scratch);
    float* Q0 = g + 0 * U;
    float* K0 = g + 1 * U;
    float* V0 = g + 2 * U;
    float* Q1 = g + 3 * U;
    float* K1 = g + 4 * U;
    float* V1 = g + 5 * U;
    float* C0 = g + 6 * U;
    float* C1 = g + 7 * U;
    float* C2 = g + 8 * U;
    float* C3 = g + 9 * U;
    float* OUTCAT = g + 10 * U;  // [8192 x 1024]
    float* OUTB   = g + 12 * U;  // [8192 x 512]
    float* QKV    = g + 13 * U;  // [8192 x 1536]

    static int smem_set = 0;
    const int FSMEM = 4 * 64 * FPAD * sizeof(float);  // 73728
    if (!smem_set) {
        cudaFuncSetAttribute(flash64_mma, cudaFuncAttributeMaxDynamicSharedMemorySize, FSMEM);
        smem_set = 1;
    }

    const dim3 gblk(256);
    const dim3 g512(HDIM / 128, MTOT / 128);      // (4,64)
    const dim3 g1536(3 * HDIM / 128, MTOT / 128); // (12,64)
    const dim3 fblk(128);
    const dim3 fg(SEQL / 64, NHEAD, BATCH);

    // 1) QKV projections
    gemm_tf32<<<g512, gblk>>>(hs,  nullptr, 1.f, HDIM, w_q_img, b_q_img, Q0, HDIM, HDIM);
    gemm_tf32<<<g512, gblk>>>(hs,  nullptr, 1.f, HDIM, w_k_img, b_k_img, K0, HDIM, HDIM);
    gemm_tf32<<<g512, gblk>>>(hs,  nullptr, 1.f, HDIM, w_v_img, b_v_img, V0, HDIM, HDIM);
    gemm_tf32<<<g512, gblk>>>(txt, nullptr, 1.f, HDIM, w_q_txt, b_q_txt, Q1, HDIM, HDIM);
    gemm_tf32<<<g512, gblk>>>(txt, nullptr, 1.f, HDIM, w_k_txt, b_k_txt, K1, HDIM, HDIM);
    gemm_tf32<<<g512, gblk>>>(txt, nullptr, 1.f, HDIM, w_v_txt, b_v_txt, V1, HDIM, HDIM);

    // 2) Four attentions
    flash64_mma<<<fg, fblk, FSMEM>>>(Q0, K0, V0, C0, HDIM, HDIM, HDIM);
    flash64_mma<<<fg, fblk, FSMEM>>>(Q1, K1, V1, C1, HDIM, HDIM, HDIM);
    flash64_mma<<<fg, fblk, FSMEM>>>(Q0, K1, V1, C2, HDIM, HDIM, HDIM);
    flash64_mma<<<fg, fblk, FSMEM>>>(Q1, K0, V0, C3, HDIM, HDIM, HDIM);

    // 3) out_img / out_txt with fused (a+b)*0.5, written into concat halves
    gemm_tf32<<<g512, gblk>>>(C0, C2, 0.5f, HDIM, w_out_img, b_out_img, OUTCAT,        2 * HDIM, HDIM);
    gemm_tf32<<<g512, gblk>>>(C1, C3, 0.5f, HDIM, w_out_txt, b_out_txt, OUTCAT + HDIM, 2 * HDIM, HDIM);

    // 4) cat linear
    gemm_tf32<<<g512, gblk>>>(OUTCAT, nullptr, 1.f, 2 * HDIM, w_cat, b_cat, OUTB, HDIM, 2 * HDIM);

    // 5) pooling in_proj -> QKV [8192,1536]
    gemm_tf32<<<g1536, gblk>>>(OUTB, nullptr, 1.f, HDIM, in_proj_w, in_proj_b, QKV, 3 * HDIM, HDIM);

    // 6) pooling self-attention (strided views of QKV)
    flash64_mma<<<fg, fblk, FSMEM>>>(QKV, QKV + HDIM, QKV + 2 * HDIM, C0, 3 * HDIM, 3 * HDIM, HDIM);

    // 7) out_proj -> final output
    gemm_tf32<<<g512, gblk>>>(C0, nullptr, 1.f, HDIM, out_proj_w, out_proj_b, out, HDIM, HDIM);
}

// round 3
// speedup vs baseline: 2.3356x; 1.2017x over previous
#include <cuda_runtime.h>
#include <math.h>
#include <stdint.h>

// Problem constants
#define HDIM 512
#define NHEAD 8
#define HEADD 64
#define BATCH 8
#define SEQL 1024
#define MTOT (BATCH * SEQL)  // 8192

// Scratch: 16 units of [8192 x 512] floats = 268 MB
__device__ float g_scratch[(size_t)16 * 8192 * 512];

// fp32 -> tf32 (round-to-nearest) bit pattern
__device__ __forceinline__ float f2tf32(float x) {
    float y;
    asm("cvt.rna.tf32.f32 %0, %1;" : "=f"(y) : "f"(x));
    return y;
}

// m16n8k8 TF32 HMMA, fp32 accumulate (D += A*B)
__device__ __forceinline__ void mma_tf32(float& d0, float& d1, float& d2, float& d3,
                                         uint32_t a0, uint32_t a1, uint32_t a2, uint32_t a3,
                                         uint32_t b0, uint32_t b1)
{
    asm volatile(
        "mma.sync.aligned.m16n8k8.row.col.f32.tf32.tf32.f32 "
        "{%0,%1,%2,%3}, {%4,%5,%6,%7}, {%8,%9}, {%0,%1,%2,%3};"
        : "+f"(d0), "+f"(d1), "+f"(d2), "+f"(d3)
        : "r"(a0), "r"(a1), "r"(a2), "r"(a3), "r"(b0), "r"(b1));
}

// ldmatrix x4 (b16 view): four 8x8-b16 (= 8x4-tf32) tiles; lane l gets [l/4][l%4]
__device__ __forceinline__ void ldsm4(uint32_t& r0, uint32_t& r1, uint32_t& r2, uint32_t& r3,
                                      uint32_t addr)
{
    asm volatile("ldmatrix.sync.aligned.m8n8.x4.shared.b16 {%0,%1,%2,%3}, [%4];"
                 : "=r"(r0), "=r"(r1), "=r"(r2), "=r"(r3) : "r"(addr));
}

// ---------------------------------------------------------------------------
// TF32 GEMM (NT): C[m,n] = sum_k scaleA*(A1[m,k]+A2[m,k]) * W[n,k] + bias[n]
// CTA tile 128x128, BK=32, 256 threads (8 warps 2x4; warp tile 64x32).
// Double-buffered smem (dynamic, 72KB), register prefetch, ldmatrix fragments.
// ---------------------------------------------------------------------------
#define GPAD 36
__global__ __launch_bounds__(256)
void gemm_tf32(const float* __restrict__ A1, const float* __restrict__ A2,
               float scaleA, int lda,
               const float* __restrict__ W, const float* __restrict__ bias,
               float* __restrict__ C, int ldc, int K)
{
    extern __shared__ float sm[];
    const int bm = blockIdx.y * 128;
    const int bn = blockIdx.x * 128;
    const int tid = threadIdx.x;
    const int warp = tid >> 5;
    const int lane = tid & 31;
    const int g = lane >> 2;
    const int t = lane & 3;
    const int wm = warp >> 2;   // 0..1
    const int wn = warp & 3;    // 0..3

    const int lrow = tid >> 1;          // 0..127
    const int lcb  = (tid & 1) * 16;    // 0 or 16

    float* Af[2] = { sm,                 sm + 2 * 128 * GPAD };
    float* Wf[2] = { sm + 128 * GPAD,    sm + 3 * 128 * GPAD };
    const uint32_t smb = (uint32_t)__cvta_generic_to_shared(sm);
    const uint32_t bufsz = 128 * GPAD * 4;
    const uint32_t Ab[2] = { smb,          smb + 2 * bufsz };
    const uint32_t Wb[2] = { smb + bufsz,  smb + 3 * bufsz };

    // lane-dependent ldmatrix offsets (bytes)
    const uint32_t aoff = ((lane & 15) * GPAD + ((lane >> 4) & 1) * 4) * 4;
    const uint32_t boff = ((lane & 7) * GPAD + ((lane >> 3) & 3) * 4) * 4;

    float acc[4][4][4] = {};
    float4 ar[4], wr[4];

    const int NK = K >> 5;

    // prologue: LDG tile 0
    {
        const float* pa = A1 + (size_t)(bm + lrow) * lda + lcb;
        const float* pw = W  + (size_t)(bn + lrow) * K + lcb;
        #pragma unroll
        for (int u = 0; u < 4; u++) {
            float4 v = *(const float4*)(pa + 4 * u);
            if (A2) {
                float4 v2 = *(const float4*)(A2 + (size_t)(bm + lrow) * lda + lcb + 4 * u);
                v.x += v2.x; v.y += v2.y; v.z += v2.z; v.w += v2.w;
            }
            ar[u] = v;
            wr[u] = *(const float4*)(pw + 4 * u);
        }
    }

    for (int i = 0; i < NK; i++) {
        const int cur = i & 1;
        // STS staged regs (rounded) into buf cur
        {
            float* As = Af[cur];
            float* Ws = Wf[cur];
            #pragma unroll
            for (int u = 0; u < 4; u++) {
                float4 a4;
                a4.x = f2tf32(ar[u].x * scaleA); a4.y = f2tf32(ar[u].y * scaleA);
                a4.z = f2tf32(ar[u].z * scaleA); a4.w = f2tf32(ar[u].w * scaleA);
                *(float4*)&As[lrow * GPAD + lcb + 4 * u] = a4;
                float4 w4;
                w4.x = f2tf32(wr[u].x); w4.y = f2tf32(wr[u].y);
                w4.z = f2tf32(wr[u].z); w4.w = f2tf32(wr[u].w);
                *(float4*)&Ws[lrow * GPAD + lcb + 4 * u] = w4;
            }
        }
        __syncthreads();

        // prefetch next tile into regs (overlaps compute)
        if (i + 1 < NK) {
            const int k0 = (i + 1) * 32;
            const float* pa = A1 + (size_t)(bm + lrow) * lda + k0 + lcb;
            const float* pw = W  + (size_t)(bn + lrow) * K + k0 + lcb;
            #pragma unroll
            for (int u = 0; u < 4; u++) {
                float4 v = *(const float4*)(pa + 4 * u);
                if (A2) {
                    float4 v2 = *(const float4*)(A2 + (size_t)(bm + lrow) * lda + k0 + lcb + 4 * u);
                    v.x += v2.x; v.y += v2.y; v.z += v2.z; v.w += v2.w;
                }
                ar[u] = v;
                wr[u] = *(const float4*)(pw + 4 * u);
            }
        }

        // compute buf cur: 4 k8-steps via ldmatrix fragments
        const uint32_t Abase = Ab[cur] + aoff;
        const uint32_t Wbase = Wb[cur] + boff;
        #pragma unroll
        for (int p = 0; p < 2; p++) {
            uint32_t bfr[4][4];
            #pragma unroll
            for (int nt = 0; nt < 4; nt++)
                ldsm4(bfr[nt][0], bfr[nt][1], bfr[nt][2], bfr[nt][3],
                      Wbase + ((wn * 32 + nt * 8) * GPAD + 16 * p) * 4);
            #pragma unroll
            for (int hlf = 0; hlf < 2; hlf++) {
                const int k8 = 2 * p + hlf;
                uint32_t a[4][4];
                #pragma unroll
                for (int mt = 0; mt < 4; mt++)
                    ldsm4(a[mt][0], a[mt][1], a[mt][2], a[mt][3],
                          Abase + ((wm * 64 + mt * 16) * GPAD + k8 * 8) * 4);
                #pragma unroll
                for (int nt = 0; nt < 4; nt++)
                    #pragma unroll
                    for (int mt = 0; mt < 4; mt++)
                        mma_tf32(acc[mt][nt][0], acc[mt][nt][1], acc[mt][nt][2], acc[mt][nt][3],
                                 a[mt][0], a[mt][1], a[mt][2], a[mt][3],
                                 bfr[nt][2 * hlf], bfr[nt][2 * hlf + 1]);
            }
        }
        __syncthreads();
    }

    // Epilogue: bias + store
    #pragma unroll
    for (int mt = 0; mt < 4; mt++) {
        const int r = bm + wm * 64 + mt * 16 + g;
        #pragma unroll
        for (int nt = 0; nt < 4; nt++) {
            const int col = bn + wn * 32 + nt * 8 + 2 * t;
            const float bx = bias[col], by = bias[col + 1];
            *(float2*)(C + (size_t)r * ldc + col) =
                make_float2(acc[mt][nt][0] + bx, acc[mt][nt][1] + by);
            *(float2*)(C + (size_t)(r + 8) * ldc + col) =
                make_float2(acc[mt][nt][2] + bx, acc[mt][nt][3] + by);
        }
    }
}

// ---------------------------------------------------------------------------
// TF32-MMA flash attention, HD=64, BQ=128, BK=64, 8 warps (256 threads).
// Q fragments in registers; K fragments via ldmatrix; V via conflict-free LDS;
// P fragments rebuilt with quad shuffles (no smem round-trip).
// Grid: (L/128, NH, B). Static smem ~35KB.
// ---------------------------------------------------------------------------
#define KPAD 68
#define VPAD 72
__global__ __launch_bounds__(256)
void flash128(const float* __restrict__ Q, const float* __restrict__ K,
              const float* __restrict__ V, float* __restrict__ O,
              int sq, int skv, int so)
{
    __shared__ float Ks[64 * KPAD];
    __shared__ float Vs[64 * VPAD];

    const int q0 = blockIdx.x * 128;
    const int h  = blockIdx.y;
    const int b  = blockIdx.z;
    const int tid = threadIdx.x;
    const int w = tid >> 5;
    const int lane = tid & 31;
    const int g = lane >> 2;
    const int t = lane & 3;

    const float* Qb = Q + (size_t)b * SEQL * sq  + (size_t)h * HEADD;
    const float* Kb = K + (size_t)b * SEQL * skv + (size_t)h * HEADD;
    const float* Vb = V + (size_t)b * SEQL * skv + (size_t)h * HEADD;
    float*       Ob = O + (size_t)b * SEQL * so  + (size_t)h * HEADD;

    // Q fragments in registers (row-block 16w, scaled by 1/8, rounded)
    uint32_t qa[8][4];
    {
        const float* q0p = Qb + (size_t)(q0 + 16 * w + g) * sq;
        const float* q8p = q0p + (size_t)8 * sq;
        #pragma unroll
        for (int k8 = 0; k8 < 8; k8++) {
            qa[k8][0] = __float_as_uint(f2tf32(q0p[8 * k8 + t]     * 0.125f));
            qa[k8][1] = __float_as_uint(f2tf32(q8p[8 * k8 + t]     * 0.125f));
            qa[k8][2] = __float_as_uint(f2tf32(q0p[8 * k8 + t + 4] * 0.125f));
            qa[k8][3] = __float_as_uint(f2tf32(q8p[8 * k8 + t + 4] * 0.125f));
        }
    }

    const uint32_t smK = (uint32_t)__cvta_generic_to_shared(Ks);
    const uint32_t koff = ((lane & 7) * KPAD + ((lane >> 3) & 3) * 4) * 4;

    const int srow = tid >> 2;          // 0..63
    const int scol = (tid & 3) * 16;

    float oacc[8][4] = {};
    float mi0 = -INFINITY, mi1 = -INFINITY;
    float li0 = 0.f, li1 = 0.f;

    float4 kr[4], vr[4];
    // prologue: LDG K/V tile 0
    {
        const float* pk = Kb + (size_t)srow * skv + scol;
        const float* pv = Vb + (size_t)srow * skv + scol;
        #pragma unroll
        for (int u = 0; u < 4; u++) { kr[u] = *(const float4*)(pk + 4 * u);
                                      vr[u] = *(const float4*)(pv + 4 * u); }
    }

    for (int kt = 0; kt < SEQL; kt += 64) {
        // STS staged tile (rounded)
        #pragma unroll
        for (int u = 0; u < 4; u++) {
            float4 k4;
            k4.x = f2tf32(kr[u].x); k4.y = f2tf32(kr[u].y);
            k4.z = f2tf32(kr[u].z); k4.w = f2tf32(kr[u].w);
            *(float4*)&Ks[srow * KPAD + scol + 4 * u] = k4;
            float4 v4;
            v4.x = f2tf32(vr[u].x); v4.y = f2tf32(vr[u].y);
            v4.z = f2tf32(vr[u].z); v4.w = f2tf32(vr[u].w);
            *(float4*)&Vs[srow * VPAD + scol + 4 * u] = v4;
        }
        __syncthreads();

        // prefetch next K/V tile
        if (kt + 64 < SEQL) {
            const float* pk = Kb + (size_t)(kt + 64 + srow) * skv + scol;
            const float* pv = Vb + (size_t)(kt + 64 + srow) * skv + scol;
            #pragma unroll
            for (int u = 0; u < 4; u++) { kr[u] = *(const float4*)(pk + 4 * u);
                                          vr[u] = *(const float4*)(pv + 4 * u); }
        }

        // S = (Q/8) @ K^T
        float sacc[8][4] = {};
        #pragma unroll
        for (int p = 0; p < 4; p++) {
            #pragma unroll
            for (int nt = 0; nt < 8; nt++) {
                uint32_t b0, b1, b2, b3;
                ldsm4(b0, b1, b2, b3, smK + (nt * 8 * KPAD + 16 * p) * 4 + koff);
                mma_tf32(sacc[nt][0], sacc[nt][1], sacc[nt][2], sacc[nt][3],
                         qa[2 * p][0], qa[2 * p][1], qa[2 * p][2], qa[2 * p][3], b0, b1);
                mma_tf32(sacc[nt][0], sacc[nt][1], sacc[nt][2], sacc[nt][3],
                         qa[2 * p + 1][0], qa[2 * p + 1][1], qa[2 * p + 1][2], qa[2 * p + 1][3], b2, b3);
            }
        }

        // Online softmax (rows g and g+8; reduce across the 4 lanes of a quad)
        {
            float mx0 = -INFINITY, mx1 = -INFINITY;
            #pragma unroll
            for (int nt = 0; nt < 8; nt++) {
                mx0 = fmaxf(mx0, fmaxf(sacc[nt][0], sacc[nt][1]));
                mx1 = fmaxf(mx1, fmaxf(sacc[nt][2], sacc[nt][3]));
            }
            mx0 = fmaxf(mx0, __shfl_xor_sync(0xffffffffu, mx0, 1, 4));
            mx0 = fmaxf(mx0, __shfl_xor_sync(0xffffffffu, mx0, 2, 4));
            mx1 = fmaxf(mx1, __shfl_xor_sync(0xffffffffu, mx1, 1, 4));
            mx1 = fmaxf(mx1, __shfl_xor_sync(0xffffffffu, mx1, 2, 4));
            float mn0 = fmaxf(mi0, mx0);
            float mn1 = fmaxf(mi1, mx1);
            float c0 = __expf(mi0 - mn0);
            float c1 = __expf(mi1 - mn1);
            mi0 = mn0; mi1 = mn1;
            float rs0 = 0.f, rs1 = 0.f;
            #pragma unroll
            for (int nt = 0; nt < 8; nt++) {
                sacc[nt][0] = __expf(sacc[nt][0] - mn0);
                sacc[nt][1] = __expf(sacc[nt][1] - mn0);
                sacc[nt][2] = __expf(sacc[nt][2] - mn1);
                sacc[nt][3] = __expf(sacc[nt][3] - mn1);
                rs0 += sacc[nt][0] + sacc[nt][1];
                rs1 += sacc[nt][2] + sacc[nt][3];
            }
            rs0 += __shfl_xor_sync(0xffffffffu, rs0, 1, 4);
            rs0 += __shfl_xor_sync(0xffffffffu, rs0, 2, 4);
            rs1 += __shfl_xor_sync(0xffffffffu, rs1, 1, 4);
            rs1 += __shfl_xor_sync(0xffffffffu, rs1, 2, 4);
            li0 = li0 * c0 + rs0;
            li1 = li1 * c1 + rs1;
            #pragma unroll
            for (int nt = 0; nt < 8; nt++) {
                oacc[nt][0] *= c0; oacc[nt][1] *= c0;
                oacc[nt][2] *= c1; oacc[nt][3] *= c1;
            }
        }

        // O += P @ V : P fragments via quad shuffles (no smem round-trip)
        {
            const int lsrc0 = (g << 2) + (t >> 1);
            #pragma unroll
            for (int k8 = 0; k8 < 8; k8++) {
                float v00 = __shfl_sync(0xffffffffu, sacc[k8][0], lsrc0);
                float v01 = __shfl_sync(0xffffffffu, sacc[k8][1], lsrc0);
                float v10 = __shfl_sync(0xffffffffu, sacc[k8][2], lsrc0);
                float v11 = __shfl_sync(0xffffffffu, sacc[k8][3], lsrc0);
                float w00 = __shfl_sync(0xffffffffu, sacc[k8][0], lsrc0 + 2);
                float w01 = __shfl_sync(0xffffffffu, sacc[k8][1], lsrc0 + 2);
                float w10 = __shfl_sync(0xffffffffu, sacc[k8][2], lsrc0 + 2);
                float w11 = __shfl_sync(0xffffffffu, sacc[k8][3], lsrc0 + 2);
                const uint32_t a0 = __float_as_uint((t & 1) ? v01 : v00);
                const uint32_t a1 = __float_as_uint((t & 1) ? v11 : v10);
                const uint32_t a2 = __float_as_uint((t & 1) ? w01 : w00);
                const uint32_t a3 = __float_as_uint((t & 1) ? w11 : w10);
                #pragma unroll
                for (int nt = 0; nt < 8; nt++) {
                    const uint32_t b0 = __float_as_uint(Vs[(k8 * 8 + t) * VPAD + nt * 8 + g]);
                    const uint32_t b1 = __float_as_uint(Vs[(k8 * 8 + t + 4) * VPAD + nt * 8 + g]);
                    mma_tf32(oacc[nt][0], oacc[nt][1], oacc[nt][2], oacc[nt][3],
                             a0, a1, a2, a3, b0, b1);
                }
            }
        }
        __syncthreads();
    }

    // Epilogue: O / l
    {
        const float inv0 = 1.0f / li0;
        const float inv1 = 1.0f / li1;
        const int r0 = q0 + 16 * w + g;
        #pragma unroll
        for (int nt = 0; nt < 8; nt++) {
            const int col = nt * 8 + 2 * t;
            *(float2*)(Ob + (size_t)r0 * so + col) =
                make_float2(oacc[nt][0] * inv0, oacc[nt][1] * inv0);
            *(float2*)(Ob + (size_t)(r0 + 8) * so + col) =
                make_float2(oacc[nt][2] * inv1, oacc[nt][3] * inv1);
        }
    }
}

// ---------------------------------------------------------------------------
extern "C" void kernel_launch(void* const* d_in, const int* in_sizes, int n_in,
                              void* d_out, int out_size)
{
    (void)in_sizes; (void)n_in; (void)out_size;

    const float* hs        = (const float*)d_in[0];
    const float* txt       = (const float*)d_in[1];
    const float* w_q_img   = (const float*)d_in[2];
    const float* b_q_img   = (const float*)d_in[3];
    const float* w_k_img   = (const float*)d_in[4];
    const float* b_k_img   = (const float*)d_in[5];
    const float* w_v_img   = (const float*)d_in[6];
    const float* b_v_img   = (const float*)d_in[7];
    const float* w_q_txt   = (const float*)d_in[8];
    const float* b_q_txt   = (const float*)d_in[9];
    const float* w_k_txt   = (const float*)d_in[10];
    const float* b_k_txt   = (const float*)d_in[11];
    const float* w_v_txt   = (const float*)d_in[12];
    const float* b_v_txt   = (const float*)d_in[13];
    const float* w_out_img = (const float*)d_in[14];
    const float* b_out_img = (const float*)d_in[15];
    const float* w_out_txt = (const float*)d_in[16];
    const float* b_out_txt = (const float*)d_in[17];
    const float* w_cat     = (const float*)d_in[18];
    const float* b_cat     = (const float*)d_in[19];
    const float* in_proj_w = (const float*)d_in[20];
    const float* in_proj_b = (const float*)d_in[21];
    const float* out_proj_w= (const float*)d_in[22];
    const float* out_proj_b= (const float*)d_in[23];
    float* out = (float*)d_out;

    constexpr size_t U = (size_t)MTOT * HDIM;  // 8192*512
    float* g;
    cudaGetSymbolAddress((void**)&g, g_scratch);
    float* Q0 = g + 0 * U;
    float* K0 = g + 1 * U;
    float* V0 = g + 2 * U;
    float* Q1 = g + 3 * U;
    float* K1 = g + 4 * U;
    float* V1 = g + 5 * U;
    float* C0 = g + 6 * U;
    float* C1 = g + 7 * U;
    float* C2 = g + 8 * U;
    float* C3 = g + 9 * U;
    float* OUTCAT = g + 10 * U;  // [8192 x 1024]
    float* OUTB   = g + 12 * U;  // [8192 x 512]
    float* QKV    = g + 13 * U;  // [8192 x 1536]

    const int GSMEM = 4 * 128 * GPAD * sizeof(float);  // 73728
    cudaFuncSetAttribute(gemm_tf32, cudaFuncAttributeMaxDynamicSharedMemorySize, GSMEM);

    const dim3 gblk(256);
    const dim3 g512(HDIM / 128, MTOT / 128);      // (4,64)
    const dim3 g1536(3 * HDIM / 128, MTOT / 128); // (12,64)
    const dim3 fblk(256);
    const dim3 fg(SEQL / 128, NHEAD, BATCH);      // (8,8,8)

    // 1) QKV projections
    gemm_tf32<<<g512, gblk, GSMEM>>>(hs,  nullptr, 1.f, HDIM, w_q_img, b_q_img, Q0, HDIM, HDIM);
    gemm_tf32<<<g512, gblk, GSMEM>>>(hs,  nullptr, 1.f, HDIM, w_k_img, b_k_img, K0, HDIM, HDIM);
    gemm_tf32<<<g512, gblk, GSMEM>>>(hs,  nullptr, 1.f, HDIM, w_v_img, b_v_img, V0, HDIM, HDIM);
    gemm_tf32<<<g512, gblk, GSMEM>>>(txt, nullptr, 1.f, HDIM, w_q_txt, b_q_txt, Q1, HDIM, HDIM);
    gemm_tf32<<<g512, gblk, GSMEM>>>(txt, nullptr, 1.f, HDIM, w_k_txt, b_k_txt, K1, HDIM, HDIM);
    gemm_tf32<<<g512, gblk, GSMEM>>>(txt, nullptr, 1.f, HDIM, w_v_txt, b_v_txt, V1, HDIM, HDIM);

    // 2) Four attentions
    flash128<<<fg, fblk>>>(Q0, K0, V0, C0, HDIM, HDIM, HDIM);
    flash128<<<fg, fblk>>>(Q1, K1, V1, C1, HDIM, HDIM, HDIM);
    flash128<<<fg, fblk>>>(Q0, K1, V1, C2, HDIM, HDIM, HDIM);
    flash128<<<fg, fblk>>>(Q1, K0, V0, C3, HDIM, HDIM, HDIM);

    // 3) out_img / out_txt with fused (a+b)*0.5, written into concat halves
    gemm_tf32<<<g512, gblk, GSMEM>>>(C0, C2, 0.5f, HDIM, w_out_img, b_out_img, OUTCAT,        2 * HDIM, HDIM);
    gemm_tf32<<<g512, gblk, GSMEM>>>(C1, C3, 0.5f, HDIM, w_out_txt, b_out_txt, OUTCAT + HDIM, 2 * HDIM, HDIM);

    // 4) cat linear
    gemm_tf32<<<g512, gblk, GSMEM>>>(OUTCAT, nullptr, 1.f, 2 * HDIM, w_cat, b_cat, OUTB, HDIM, 2 * HDIM);

    // 5) pooling in_proj -> QKV [8192,1536]
    gemm_tf32<<<g1536, gblk, GSMEM>>>(OUTB, nullptr, 1.f, HDIM, in_proj_w, in_proj_b, QKV, 3 * HDIM, HDIM);

    // 6) pooling self-attention (strided views of QKV)
    flash128<<<fg, fblk>>>(QKV, QKV + HDIM, QKV + 2 * HDIM, C0, 3 * HDIM, 3 * HDIM, HDIM);

    // 7) out_proj -> final output
    gemm_tf32<<<g512, gblk, GSMEM>>>(C0, nullptr, 1.f, HDIM, out_proj_w, out_proj_b, out, HDIM, HDIM);
}

// round 4
// speedup vs baseline: 3.2439x; 1.3889x over previous
#include <cuda_runtime.h>
#include <math.h>
#include <stdint.h>

// Problem constants
#define HDIM 512
#define NHEAD 8
#define HEADD 64
#define BATCH 8
#define SEQL 1024
#define MTOT 8192

// Scratch: 17 units of [8192 x 512] floats
__device__ float g_scratch[(size_t)17 * 8192 * 512];

// ---------------------------------------------------------------------------
// Helpers
// ---------------------------------------------------------------------------
__device__ __forceinline__ float f2tf32(float x) {
    float y; asm("cvt.rna.tf32.f32 %0, %1;" : "=f"(y) : "f"(x)); return y;
}

__device__ __forceinline__ void mma_tf32(float& d0, float& d1, float& d2, float& d3,
                                         uint32_t a0, uint32_t a1, uint32_t a2, uint32_t a3,
                                         uint32_t b0, uint32_t b1)
{
    asm volatile(
        "mma.sync.aligned.m16n8k8.row.col.f32.tf32.tf32.f32 "
        "{%0,%1,%2,%3}, {%4,%5,%6,%7}, {%8,%9}, {%0,%1,%2,%3};"
        : "+f"(d0), "+f"(d1), "+f"(d2), "+f"(d3)
        : "r"(a0), "r"(a1), "r"(a2), "r"(a3), "r"(b0), "r"(b1));
}

__device__ __forceinline__ void ldsm4(uint32_t& r0, uint32_t& r1, uint32_t& r2, uint32_t& r3,
                                      uint32_t addr)
{
    asm volatile("ldmatrix.sync.aligned.m8n8.x4.shared.b16 {%0,%1,%2,%3}, [%4];"
                 : "=r"(r0), "=r"(r1), "=r"(r2), "=r"(r3) : "r"(addr));
}

__device__ __forceinline__ void cp16(uint32_t dst, const void* src) {
    asm volatile("cp.async.cg.shared.global [%0], [%1], 16;" :: "r"(dst), "l"(src));
}
__device__ __forceinline__ void cpcommit() { asm volatile("cp.async.commit_group;"); }
template<int N> __device__ __forceinline__ void cpwait() {
    asm volatile("cp.async.wait_group %0;" :: "n"(N));
}

// round-half-up into tf32 (HW truncates low 13 bits of mma operands)
#define FRND(u) ((u) + 0x1000u)

// exact tf32 round of a float value (round-half-up + mask)
__device__ __forceinline__ float rndtf(float x) {
    return __uint_as_float((__float_as_uint(x) + 0x1000u) & 0xFFFFE000u);
}

// ---------------------------------------------------------------------------
// TF32 GEMM (NT), CTA 128x128, BK=32, 256 thr, cp.async 2-stage pipeline.
// Weight segments of 512 columns select (W0,B0)/(W1,B1)/(W2,B2).
// FUSED: A = scaleA*(A1+A2), register-staged with cvt; else cp.async raw +
// fragment rounding.
// ---------------------------------------------------------------------------
#define GPAD 36
struct GemmP {
    const float *A1, *A2; float scaleA; int lda;
    const float *W0, *W1, *W2, *B0, *B1, *B2;
    float* C; int ldc; int K;
};

template<bool FUSED>
__global__ __launch_bounds__(256, 2) void gemm_k(GemmP P)
{
    extern __shared__ float sm[];
    const int bm  = blockIdx.y * 128;
    const int bnG = blockIdx.x * 128;
    const int seg = bnG >> 9;
    const float* W  = seg == 0 ? P.W0 : (seg == 1 ? P.W1 : P.W2);
    const float* BI = seg == 0 ? P.B0 : (seg == 1 ? P.B1 : P.B2);
    const int bn = bnG & 511;

    const int tid  = threadIdx.x;
    const int warp = tid >> 5;
    const int lane = tid & 31;
    const int g = lane >> 2;
    const int t = lane & 3;
    const int wm = warp >> 2;
    const int wn = warp & 3;

    const uint32_t smb  = (uint32_t)__cvta_generic_to_shared(sm);
    const uint32_t bufB = 128 * GPAD * 4;
    // layout: [A0][W0][A1][W1]

    const uint32_t aoff = ((lane & 15) * GPAD + ((lane >> 4) & 1) * 4) * 4;
    const uint32_t boff = ((lane & 7) * GPAD + ((lane >> 3) & 3) * 4) * 4;

    const int crow = tid >> 3;        // 0..31
    const int cch  = (tid & 7) * 4;   // float col for 16B chunk

    const int NK = P.K >> 5;
    float acc[4][4][4] = {};

    // staging helpers -------------------------------------------------------
    auto issueW = [&](int i) {
        const int k0 = i * 32;
        const uint32_t dst = smb + (2 * (i & 1) + 1) * bufB;
        #pragma unroll
        for (int u = 0; u < 4; u++) {
            const int r = crow + 32 * u;
            cp16(dst + ((uint32_t)r * GPAD + cch) * 4,
                 W + (size_t)(bn + r) * P.K + k0 + cch);
        }
    };
    auto issueA = [&](int i) {
        const int k0 = i * 32;
        const uint32_t dst = smb + (2 * (i & 1)) * bufB;
        #pragma unroll
        for (int u = 0; u < 4; u++) {
            const int r = crow + 32 * u;
            cp16(dst + ((uint32_t)r * GPAD + cch) * 4,
                 P.A1 + (size_t)(bm + r) * P.lda + k0 + cch);
        }
    };
    const int lrow = tid >> 1;
    const int lcb  = (tid & 1) * 16;
    auto stageA_reg = [&](int i) {  // FUSED path: (A1+A2)*scale, cvt, STS
        const int k0 = i * 32;
        float* As = sm + (size_t)(2 * (i & 1)) * 128 * GPAD;
        const float* p1 = P.A1 + (size_t)(bm + lrow) * P.lda + k0 + lcb;
        const float* p2 = P.A2 + (size_t)(bm + lrow) * P.lda + k0 + lcb;
        #pragma unroll
        for (int u = 0; u < 4; u++) {
            float4 v = *(const float4*)(p1 + 4 * u);
            float4 w = *(const float4*)(p2 + 4 * u);
            float4 o;
            o.x = f2tf32((v.x + w.x) * P.scaleA);
            o.y = f2tf32((v.y + w.y) * P.scaleA);
            o.z = f2tf32((v.z + w.z) * P.scaleA);
            o.w = f2tf32((v.w + w.w) * P.scaleA);
            *(float4*)&As[lrow * GPAD + lcb + 4 * u] = o;
        }
    };

    // prologue
    if (FUSED) { issueW(0); cpcommit(); stageA_reg(0); }
    else       { issueA(0); issueW(0); cpcommit(); }

    for (int i = 0; i < NK; i++) {
        if (i + 1 < NK) {
            if (!FUSED) issueA(i + 1);
            issueW(i + 1);
            cpcommit();
            cpwait<1>();
        } else {
            cpwait<0>();
        }
        __syncthreads();

        // compute buffer i&1
        const uint32_t Ab = smb + (2 * (i & 1)) * bufB + aoff;
        const uint32_t Wb = smb + (2 * (i & 1) + 1) * bufB + boff;
        #pragma unroll
        for (int p = 0; p < 2; p++) {
            uint32_t bfr[4][4];
            #pragma unroll
            for (int nt = 0; nt < 4; nt++) {
                ldsm4(bfr[nt][0], bfr[nt][1], bfr[nt][2], bfr[nt][3],
                      Wb + ((wn * 32 + nt * 8) * GPAD + 16 * p) * 4);
                bfr[nt][0] = FRND(bfr[nt][0]); bfr[nt][1] = FRND(bfr[nt][1]);
                bfr[nt][2] = FRND(bfr[nt][2]); bfr[nt][3] = FRND(bfr[nt][3]);
            }
            #pragma unroll
            for (int hlf = 0; hlf < 2; hlf++) {
                const int k8 = 2 * p + hlf;
                uint32_t a[4][4];
                #pragma unroll
                for (int mt = 0; mt < 4; mt++) {
                    ldsm4(a[mt][0], a[mt][1], a[mt][2], a[mt][3],
                          Ab + ((wm * 64 + mt * 16) * GPAD + k8 * 8) * 4);
                    a[mt][0] = FRND(a[mt][0]); a[mt][1] = FRND(a[mt][1]);
                    a[mt][2] = FRND(a[mt][2]); a[mt][3] = FRND(a[mt][3]);
                }
                #pragma unroll
                for (int nt = 0; nt < 4; nt++)
                    #pragma unroll
                    for (int mt = 0; mt < 4; mt++)
                        mma_tf32(acc[mt][nt][0], acc[mt][nt][1], acc[mt][nt][2], acc[mt][nt][3],
                                 a[mt][0], a[mt][1], a[mt][2], a[mt][3],
                                 bfr[nt][2 * hlf], bfr[nt][2 * hlf + 1]);
            }
        }

        if (FUSED && i + 1 < NK) stageA_reg(i + 1);
        __syncthreads();
    }

    // epilogue
    #pragma unroll
    for (int mt = 0; mt < 4; mt++) {
        const int r = bm + wm * 64 + mt * 16 + g;
        #pragma unroll
        for (int nt = 0; nt < 4; nt++) {
            const int cl = wn * 32 + nt * 8 + 2 * t;   // local 0..511
            const float bx = BI[bn + cl], by = BI[bn + cl + 1];
            const int col = bnG + cl;
            *(float2*)(P.C + (size_t)r * P.ldc + col) =
                make_float2(acc[mt][nt][0] + bx, acc[mt][nt][1] + by);
            *(float2*)(P.C + (size_t)(r + 8) * P.ldc + col) =
                make_float2(acc[mt][nt][2] + bx, acc[mt][nt][3] + by);
        }
    }
}

// ---------------------------------------------------------------------------
// TF32-MMA flash attention, HD=64, BQ=128, BK=64, 8 warps.
// Double-buffered K/V, one __syncthreads per tile, staging after compute.
// Multi-problem: blockIdx.z encodes (batch, combo).
// ---------------------------------------------------------------------------
#define KPAD 68
#define VPAD 72
struct FlashP {
    const float *Qp[4], *Kp[4], *Vp[4]; float* Op[4];
    int sq, skv, so, cmask, cshift;
};

__global__ __launch_bounds__(256, 2) void flash_k(FlashP P)
{
    extern __shared__ float fsm[];
    // layout: K0, K1, V0, V1
    const uint32_t smb = (uint32_t)__cvta_generic_to_shared(fsm);
    const uint32_t kbufB = 64 * KPAD * 4;
    float* Vst[2] = { fsm + 2 * 64 * KPAD, fsm + 2 * 64 * KPAD + 64 * VPAD };

    const int z = blockIdx.z;
    const int c = z & P.cmask;
    const int b = z >> P.cshift;
    const int q0 = blockIdx.x * 128;
    const int h  = blockIdx.y;

    const int tid = threadIdx.x;
    const int w = tid >> 5;
    const int lane = tid & 31;
    const int g = lane >> 2;
    const int t = lane & 3;

    const float* Qb = P.Qp[c] + (size_t)b * SEQL * P.sq  + (size_t)h * HEADD;
    const float* Kb = P.Kp[c] + (size_t)b * SEQL * P.skv + (size_t)h * HEADD;
    const float* Vb = P.Vp[c] + (size_t)b * SEQL * P.skv + (size_t)h * HEADD;
    float*       Ob = P.Op[c] + (size_t)b * SEQL * P.so  + (size_t)h * HEADD;

    // Q fragments in registers (scaled by (1/8)*log2(e), rounded)
    const float qsc = 0.125f * 1.4426950408889634f;
    uint32_t qa[8][4];
    {
        const float* q0p = Qb + (size_t)(q0 + 16 * w + g) * P.sq;
        const float* q8p = q0p + (size_t)8 * P.sq;
        #pragma unroll
        for (int k8 = 0; k8 < 8; k8++) {
            qa[k8][0] = __float_as_uint(f2tf32(q0p[8 * k8 + t]     * qsc));
            qa[k8][1] = __float_as_uint(f2tf32(q8p[8 * k8 + t]     * qsc));
            qa[k8][2] = __float_as_uint(f2tf32(q0p[8 * k8 + t + 4] * qsc));
            qa[k8][3] = __float_as_uint(f2tf32(q8p[8 * k8 + t + 4] * qsc));
        }
    }

    const uint32_t koff = ((lane & 7) * KPAD + ((lane >> 3) & 3) * 4) * 4;
    const int srow = tid >> 2;          // 0..63
    const int scol = (tid & 3) * 16;

    auto stage = [&](int kt, int s) {
        const float* pk = Kb + (size_t)(kt + srow) * P.skv + scol;
        const float* pv = Vb + (size_t)(kt + srow) * P.skv + scol;
        float* Ks = fsm + (size_t)s * 64 * KPAD;
        float* Vs = Vst[s];
        #pragma unroll
        for (int u = 0; u < 4; u++) {
            float4 k4 = *(const float4*)(pk + 4 * u);
            float4 ko;
            ko.x = f2tf32(k4.x); ko.y = f2tf32(k4.y);
            ko.z = f2tf32(k4.z); ko.w = f2tf32(k4.w);
            *(float4*)&Ks[srow * KPAD + scol + 4 * u] = ko;
            float4 v4 = *(const float4*)(pv + 4 * u);
            float4 vo;
            vo.x = f2tf32(v4.x); vo.y = f2tf32(v4.y);
            vo.z = f2tf32(v4.z); vo.w = f2tf32(v4.w);
            *(float4*)&Vs[srow * VPAD + scol + 4 * u] = vo;
        }
    };

    float oacc[8][4] = {};
    float mi0 = -INFINITY, mi1 = -INFINITY;
    float li0 = 0.f, li1 = 0.f;

    stage(0, 0);

    for (int it = 0; it < SEQL / 64; it++) {
        __syncthreads();
        const int s = it & 1;
        const uint32_t smK = smb + s * kbufB + koff;
        const float* Vs = Vst[s];

        // S = Q @ K^T (log2-domain)
        float sacc[8][4] = {};
        #pragma unroll
        for (int p = 0; p < 4; p++) {
            #pragma unroll
            for (int nt = 0; nt < 8; nt++) {
                uint32_t b0, b1, b2, b3;
                ldsm4(b0, b1, b2, b3, smK + (nt * 8 * KPAD + 16 * p) * 4);
                mma_tf32(sacc[nt][0], sacc[nt][1], sacc[nt][2], sacc[nt][3],
                         qa[2 * p][0], qa[2 * p][1], qa[2 * p][2], qa[2 * p][3], b0, b1);
                mma_tf32(sacc[nt][0], sacc[nt][1], sacc[nt][2], sacc[nt][3],
                         qa[2 * p + 1][0], qa[2 * p + 1][1], qa[2 * p + 1][2], qa[2 * p + 1][3], b2, b3);
            }
        }

        // online softmax (exp2 domain); P rounded to exact tf32
        {
            float mx0 = -INFINITY, mx1 = -INFINITY;
            #pragma unroll
            for (int nt = 0; nt < 8; nt++) {
                mx0 = fmaxf(mx0, fmaxf(sacc[nt][0], sacc[nt][1]));
                mx1 = fmaxf(mx1, fmaxf(sacc[nt][2], sacc[nt][3]));
            }
            mx0 = fmaxf(mx0, __shfl_xor_sync(0xffffffffu, mx0, 1, 4));
            mx0 = fmaxf(mx0, __shfl_xor_sync(0xffffffffu, mx0, 2, 4));
            mx1 = fmaxf(mx1, __shfl_xor_sync(0xffffffffu, mx1, 1, 4));
            mx1 = fmaxf(mx1, __shfl_xor_sync(0xffffffffu, mx1, 2, 4));
            const float mn0 = fmaxf(mi0, mx0);
            const float mn1 = fmaxf(mi1, mx1);
            const float c0 = exp2f(mi0 - mn0);
            const float c1 = exp2f(mi1 - mn1);
            mi0 = mn0; mi1 = mn1;
            float rs0 = 0.f, rs1 = 0.f;
            #pragma unroll
            for (int nt = 0; nt < 8; nt++) {
                sacc[nt][0] = rndtf(exp2f(sacc[nt][0] - mn0));
                sacc[nt][1] = rndtf(exp2f(sacc[nt][1] - mn0));
                sacc[nt][2] = rndtf(exp2f(sacc[nt][2] - mn1));
                sacc[nt][3] = rndtf(exp2f(sacc[nt][3] - mn1));
                rs0 += sacc[nt][0] + sacc[nt][1];
                rs1 += sacc[nt][2] + sacc[nt][3];
            }
            rs0 += __shfl_xor_sync(0xffffffffu, rs0, 1, 4);
            rs0 += __shfl_xor_sync(0xffffffffu, rs0, 2, 4);
            rs1 += __shfl_xor_sync(0xffffffffu, rs1, 1, 4);
            rs1 += __shfl_xor_sync(0xffffffffu, rs1, 2, 4);
            li0 = li0 * c0 + rs0;
            li1 = li1 * c1 + rs1;
            #pragma unroll
            for (int nt = 0; nt < 8; nt++) {
                oacc[nt][0] *= c0; oacc[nt][1] *= c0;
                oacc[nt][2] *= c1; oacc[nt][3] *= c1;
            }
        }

        // O += P @ V : P fragments via quad shuffles
        {
            const int lsrc0 = (g << 2) + (t >> 1);
            #pragma unroll
            for (int k8 = 0; k8 < 8; k8++) {
                float v00 = __shfl_sync(0xffffffffu, sacc[k8][0], lsrc0);
                float v01 = __shfl_sync(0xffffffffu, sacc[k8][1], lsrc0);
                float v10 = __shfl_sync(0xffffffffu, sacc[k8][2], lsrc0);
                float v11 = __shfl_sync(0xffffffffu, sacc[k8][3], lsrc0);
                float w00 = __shfl_sync(0xffffffffu, sacc[k8][0], lsrc0 + 2);
                float w01 = __shfl_sync(0xffffffffu, sacc[k8][1], lsrc0 + 2);
                float w10 = __shfl_sync(0xffffffffu, sacc[k8][2], lsrc0 + 2);
                float w11 = __shfl_sync(0xffffffffu, sacc[k8][3], lsrc0 + 2);
                const uint32_t a0 = __float_as_uint((t & 1) ? v01 : v00);
                const uint32_t a1 = __float_as_uint((t & 1) ? v11 : v10);
                const uint32_t a2 = __float_as_uint((t & 1) ? w01 : w00);
                const uint32_t a3 = __float_as_uint((t & 1) ? w11 : w10);
                #pragma unroll
                for (int nt = 0; nt < 8; nt++) {
                    const uint32_t b0 = __float_as_uint(Vs[(k8 * 8 + t) * VPAD + nt * 8 + g]);
                    const uint32_t b1 = __float_as_uint(Vs[(k8 * 8 + t + 4) * VPAD + nt * 8 + g]);
                    mma_tf32(oacc[nt][0], oacc[nt][1], oacc[nt][2], oacc[nt][3],
                             a0, a1, a2, a3, b0, b1);
                }
            }
        }

        if (it + 1 < SEQL / 64) stage((it + 1) * 64, (it + 1) & 1);
    }

    // epilogue
    {
        const float inv0 = 1.0f / li0;
        const float inv1 = 1.0f / li1;
        const int r0 = q0 + 16 * w + g;
        #pragma unroll
        for (int nt = 0; nt < 8; nt++) {
            const int col = nt * 8 + 2 * t;
            *(float2*)(Ob + (size_t)r0 * P.so + col) =
                make_float2(oacc[nt][0] * inv0, oacc[nt][1] * inv0);
            *(float2*)(Ob + (size_t)(r0 + 8) * P.so + col) =
                make_float2(oacc[nt][2] * inv1, oacc[nt][3] * inv1);
        }
    }
}

// ---------------------------------------------------------------------------
extern "C" void kernel_launch(void* const* d_in, const int* in_sizes, int n_in,
                              void* d_out, int out_size)
{
    (void)in_sizes; (void)n_in; (void)out_size;

    const float* hs        = (const float*)d_in[0];
    const float* txt       = (const float*)d_in[1];
    const float* w_q_img   = (const float*)d_in[2];
    const float* b_q_img   = (const float*)d_in[3];
    const float* w_k_img   = (const float*)d_in[4];
    const float* b_k_img   = (const float*)d_in[5];
    const float* w_v_img   = (const float*)d_in[6];
    const float* b_v_img   = (const float*)d_in[7];
    const float* w_q_txt   = (const float*)d_in[8];
    const float* b_q_txt   = (const float*)d_in[9];
    const float* w_k_txt   = (const float*)d_in[10];
    const float* b_k_txt   = (const float*)d_in[11];
    const float* w_v_txt   = (const float*)d_in[12];
    const float* b_v_txt   = (const float*)d_in[13];
    const float* w_out_img = (const float*)d_in[14];
    const float* b_out_img = (const float*)d_in[15];
    const float* w_out_txt = (const float*)d_in[16];
    const float* b_out_txt = (const float*)d_in[17];
    const float* w_cat     = (const float*)d_in[18];
    const float* b_cat     = (const float*)d_in[19];
    const float* in_proj_w = (const float*)d_in[20];
    const float* in_proj_b = (const float*)d_in[21];
    const float* out_proj_w= (const float*)d_in[22];
    const float* out_proj_b= (const float*)d_in[23];
    float* out = (float*)d_out;

    constexpr size_t U = (size_t)MTOT * HDIM;
    float* g;
    cudaGetSymbolAddress((void**)&g, g_scratch);
    float* QKV0   = g;            // [8192 x 1536]
    float* QKV1   = g + 3 * U;    // [8192 x 1536]
    float* C0     = g + 6 * U;
    float* C1     = g + 7 * U;
    float* C2     = g + 8 * U;
    float* C3     = g + 9 * U;
    float* OUTCAT = g + 10 * U;   // [8192 x 1024]
    float* OUTB   = g + 12 * U;   // [8192 x 512]
    float* QKV2   = g + 13 * U;   // [8192 x 1536]
    float* CTX    = g + 16 * U;   // [8192 x 512]

    const int GSM = 4 * 128 * GPAD * sizeof(float);                    // 73728
    const int FSM = (2 * 64 * KPAD + 2 * 64 * VPAD) * sizeof(float);   // 71680
    cudaFuncSetAttribute(gemm_k<false>, cudaFuncAttributeMaxDynamicSharedMemorySize, GSM);
    cudaFuncSetAttribute(gemm_k<true>,  cudaFuncAttributeMaxDynamicSharedMemorySize, GSM);
    cudaFuncSetAttribute(flash_k,       cudaFuncAttributeMaxDynamicSharedMemorySize, FSM);

    const dim3 blk(256);
    const dim3 g512(4, 64);
    const dim3 g1536(12, 64);

    // 1,2) merged QKV projections -> interleaved [8192 x 1536]
    {
        GemmP p{hs, nullptr, 1.f, HDIM, w_q_img, w_k_img, w_v_img,
                b_q_img, b_k_img, b_v_img, QKV0, 3 * HDIM, HDIM};
        gemm_k<false><<<g1536, blk, GSM>>>(p);
        GemmP q{txt, nullptr, 1.f, HDIM, w_q_txt, w_k_txt, w_v_txt,
                b_q_txt, b_k_txt, b_v_txt, QKV1, 3 * HDIM, HDIM};
        gemm_k<false><<<g1536, blk, GSM>>>(q);
    }

    // 3) four attentions in one launch
    {
        FlashP p;
        p.Qp[0] = QKV0;            p.Kp[0] = QKV0 + HDIM; p.Vp[0] = QKV0 + 2 * HDIM; p.Op[0] = C0;
        p.Qp[1] = QKV1;            p.Kp[1] = QKV1 + HDIM; p.Vp[1] = QKV1 + 2 * HDIM; p.Op[1] = C1;
        p.Qp[2] = QKV0;            p.Kp[2] = QKV1 + HDIM; p.Vp[2] = QKV1 + 2 * HDIM; p.Op[2] = C2;
        p.Qp[3] = QKV1;            p.Kp[3] = QKV0 + HDIM; p.Vp[3] = QKV0 + 2 * HDIM; p.Op[3] = C3;
        p.sq = 3 * HDIM; p.skv = 3 * HDIM; p.so = HDIM; p.cmask = 3; p.cshift = 2;
        flash_k<<<dim3(SEQL / 128, NHEAD, BATCH * 4), blk, FSM>>>(p);
    }

    // 4,5) out_img / out_txt fused (a+b)*0.5 -> concat halves
    {
        GemmP p{C0, C2, 0.5f, HDIM, w_out_img, nullptr, nullptr,
                b_out_img, nullptr, nullptr, OUTCAT, 2 * HDIM, HDIM};
        gemm_k<true><<<g512, blk, GSM>>>(p);
        GemmP q{C1, C3, 0.5f, HDIM, w_out_txt, nullptr, nullptr,
                b_out_txt, nullptr, nullptr, OUTCAT + HDIM, 2 * HDIM, HDIM};
        gemm_k<true><<<g512, blk, GSM>>>(q);
    }

    // 6) cat linear (K=1024)
    {
        GemmP p{OUTCAT, nullptr, 1.f, 2 * HDIM, w_cat, nullptr, nullptr,
                b_cat, nullptr, nullptr, OUTB, HDIM, 2 * HDIM};
        gemm_k<false><<<g512, blk, GSM>>>(p);
    }

    // 7) pooling in_proj (segments of one big weight)
    {
        GemmP p{OUTB, nullptr, 1.f, HDIM,
                in_proj_w, in_proj_w + 512 * 512, in_proj_w + 1024 * 512,
                in_proj_b, in_proj_b + 512,       in_proj_b + 1024,
                QKV2, 3 * HDIM, HDIM};
        gemm_k<false><<<g1536, blk, GSM>>>(p);
    }

    // 8) pooling self-attention
    {
        FlashP p;
        p.Qp[0] = QKV2; p.Kp[0] = QKV2 + HDIM; p.Vp[0] = QKV2 + 2 * HDIM; p.Op[0] = CTX;
        p.Qp[1] = p.Qp[2] = p.Qp[3] = QKV2;
        p.Kp[1] = p.Kp[2] = p.Kp[3] = QKV2 + HDIM;
        p.Vp[1] = p.Vp[2] = p.Vp[3] = QKV2 + 2 * HDIM;
        p.Op[1] = p.Op[2] = p.Op[3] = CTX;
        p.sq = 3 * HDIM; p.skv = 3 * HDIM; p.so = HDIM; p.cmask = 0; p.cshift = 0;
        flash_k<<<dim3(SEQL / 128, NHEAD, BATCH), blk, FSM>>>(p);
    }

    // 9) out_proj -> final output
    {
        GemmP p{CTX, nullptr, 1.f, HDIM, out_proj_w, nullptr, nullptr,
                out_proj_b, nullptr, nullptr, out, HDIM, HDIM};
        gemm_k<false><<<g512, blk, GSM>>>(p);
    }
}

// round 5
// speedup vs baseline: 6.9635x; 2.1467x over previous
#include <cuda_runtime.h>
#include <cuda_fp16.h>
#include <math.h>
#include <stdint.h>

#define HDIM 512
#define BATCH 8
#define SEQL 1024
#define MTOT 8192

// half scratch: 84M halves = 168MB
__device__ __half g_scratch[(size_t)84 * 1024 * 1024];

// ---------------------------------------------------------------------------
// Primitives
// ---------------------------------------------------------------------------
__device__ __forceinline__ void mma_f16(float& d0, float& d1, float& d2, float& d3,
                                        uint32_t a0, uint32_t a1, uint32_t a2, uint32_t a3,
                                        uint32_t b0, uint32_t b1)
{
    asm volatile(
        "mma.sync.aligned.m16n8k16.row.col.f32.f16.f16.f32 "
        "{%0,%1,%2,%3}, {%4,%5,%6,%7}, {%8,%9}, {%0,%1,%2,%3};"
        : "+f"(d0), "+f"(d1), "+f"(d2), "+f"(d3)
        : "r"(a0), "r"(a1), "r"(a2), "r"(a3), "r"(b0), "r"(b1));
}

__device__ __forceinline__ void ldsm4(uint32_t& r0, uint32_t& r1, uint32_t& r2, uint32_t& r3,
                                      uint32_t addr)
{
    asm volatile("ldmatrix.sync.aligned.m8n8.x4.shared.b16 {%0,%1,%2,%3}, [%4];"
                 : "=r"(r0), "=r"(r1), "=r"(r2), "=r"(r3) : "r"(addr));
}
__device__ __forceinline__ void ldsm4t(uint32_t& r0, uint32_t& r1, uint32_t& r2, uint32_t& r3,
                                       uint32_t addr)
{
    asm volatile("ldmatrix.sync.aligned.m8n8.x4.trans.shared.b16 {%0,%1,%2,%3}, [%4];"
                 : "=r"(r0), "=r"(r1), "=r"(r2), "=r"(r3) : "r"(addr));
}

__device__ __forceinline__ void cp16(uint32_t dst, const void* src) {
    asm volatile("cp.async.cg.shared.global [%0], [%1], 16;" :: "r"(dst), "l"(src));
}
__device__ __forceinline__ void cpcommit() { asm volatile("cp.async.commit_group;"); }
template<int N> __device__ __forceinline__ void cpwait() {
    asm volatile("cp.async.wait_group %0;" :: "n"(N));
}

// XOR swizzle: rows of 128B (64 halves), 16B chunk c in 0..7
__device__ __forceinline__ uint32_t swz(uint32_t r, uint32_t c) {
    return r * 128u + ((c ^ (r & 7u)) << 4);
}

__device__ __forceinline__ uint32_t packh2(float x, float y) {
    __half2 h = __floats2half2_rn(x, y);
    return *(uint32_t*)&h;
}

// ---------------------------------------------------------------------------
// fp32 -> fp16 conversion kernel (segmented table)
// ---------------------------------------------------------------------------
struct CvtP { const float* src[13]; __half* dst[13]; int nblk[13]; };

__global__ __launch_bounds__(256) void cvt_k(CvtP P)
{
    int b = blockIdx.x;
    int s = 0;
    while (b >= P.nblk[s]) { b -= P.nblk[s]; ++s; }
    size_t i = ((size_t)b * 256 + threadIdx.x) * 4;
    float4 v = *(const float4*)(P.src[s] + i);
    uint2 o;
    o.x = packh2(v.x, v.y);
    o.y = packh2(v.z, v.w);
    *(uint2*)(P.dst[s] + i) = o;
}

// ---------------------------------------------------------------------------
// FP16 GEMM (NT): C = (A or 0.5*(A1+A2)) @ W^T + bias.
// CTA 128x128, BK=64, 256 thr (8 warps 2x4, warp tile 64x32).
// cp.async 2-stage pipeline, XOR-swizzled half tiles, ldmatrix fragments.
// Weight segments of 512 output cols (W0/W1/W2, B0/B1/B2).
// ---------------------------------------------------------------------------
struct GemmP {
    const __half *A1, *A2; int lda;
    const __half *W0, *W1, *W2;
    const float  *B0, *B1, *B2;
    void* C; int ldc; int K;
};

template<bool FUSED, bool OUTF32>
__global__ __launch_bounds__(256, 2) void gemm_k(GemmP P)
{
    extern __shared__ char sm[];
    const uint32_t smb = (uint32_t)__cvta_generic_to_shared(sm);
    // buffers (16KB each): A0 @0, W0 @16K, A1 @32K, W1 @48K

    const int bm  = blockIdx.y * 128;
    const int bnG = blockIdx.x * 128;
    const int seg = bnG >> 9;
    const __half* W  = seg == 0 ? P.W0 : (seg == 1 ? P.W1 : P.W2);
    const float*  BI = seg == 0 ? P.B0 : (seg == 1 ? P.B1 : P.B2);
    const int bn = bnG & 511;

    const int tid  = threadIdx.x;
    const int warp = tid >> 5;
    const int lane = tid & 31;
    const int g = lane >> 2;
    const int t = lane & 3;
    const int wm = warp >> 2;
    const int wn = warp & 3;
    const int lr = lane & 15;
    const int lh = lane >> 4;

    const int sr = tid >> 1;        // staging row 0..127
    const int sc = (tid & 1) * 4;   // staging chunk base

    const int NK = P.K >> 6;
    float acc[4][4][4] = {};

    auto issueW = [&](int i) {
        const uint32_t dst = smb + 16384u + (uint32_t)(i & 1) * 32768u;
        const __half* src = W + (size_t)(bn + sr) * P.K + i * 64 + sc * 8;
        #pragma unroll
        for (int c = 0; c < 4; c++)
            cp16(dst + swz(sr, sc + c), src + c * 8);
    };
    auto issueA = [&](int i) {
        const uint32_t dst = smb + (uint32_t)(i & 1) * 32768u;
        const __half* src = P.A1 + (size_t)(bm + sr) * P.lda + i * 64 + sc * 8;
        #pragma unroll
        for (int c = 0; c < 4; c++)
            cp16(dst + swz(sr, sc + c), src + c * 8);
    };
    auto stageA_f = [&](int i) {   // (A1+A2)*0.5, STS half
        char* dstb = sm + (size_t)(i & 1) * 32768u;
        const __half* p1 = P.A1 + (size_t)(bm + sr) * P.lda + i * 64 + sc * 8;
        const __half* p2 = P.A2 + (size_t)(bm + sr) * P.lda + i * 64 + sc * 8;
        const __half2 hf = __float2half2_rn(0.5f);
        #pragma unroll
        for (int c = 0; c < 4; c++) {
            float4 x = *(const float4*)(p1 + c * 8);
            float4 y = *(const float4*)(p2 + c * 8);
            const __half2* xh = (const __half2*)&x;
            const __half2* yh = (const __half2*)&y;
            __half2 z[4];
            #pragma unroll
            for (int j = 0; j < 4; j++)
                z[j] = __hmul2(__hadd2(xh[j], yh[j]), hf);
            *(float4*)(dstb + swz(sr, sc + c)) = *(float4*)z;
        }
    };

    // prologue
    if (FUSED) { issueW(0); cpcommit(); stageA_f(0); }
    else       { issueA(0); issueW(0); cpcommit(); }

    for (int i = 0; i < NK; i++) {
        if (i + 1 < NK) {
            if (!FUSED) issueA(i + 1);
            issueW(i + 1);
            cpcommit();
            cpwait<1>();
        } else {
            cpwait<0>();
        }
        __syncthreads();

        const uint32_t Ab = smb + (uint32_t)(i & 1) * 32768u;
        const uint32_t Wb = smb + 16384u + (uint32_t)(i & 1) * 32768u;

        #pragma unroll
        for (int kb = 0; kb < 4; kb++) {
            uint32_t bw[2][4];
            #pragma unroll
            for (int np = 0; np < 2; np++)
                ldsm4(bw[np][0], bw[np][1], bw[np][2], bw[np][3],
                      Wb + swz(wn * 32 + np * 16 + lr, kb * 2 + lh));
            #pragma unroll
            for (int mt = 0; mt < 4; mt++) {
                uint32_t a0, a1, a2, a3;
                ldsm4(a0, a1, a2, a3, Ab + swz(wm * 64 + mt * 16 + lr, kb * 2 + lh));
                #pragma unroll
                for (int nt = 0; nt < 4; nt++) {
                    const int np = nt >> 1, hi = nt & 1;
                    mma_f16(acc[mt][nt][0], acc[mt][nt][1], acc[mt][nt][2], acc[mt][nt][3],
                            a0, a1, a2, a3,
                            bw[np][hi ? 1 : 0], bw[np][hi ? 3 : 2]);
                }
            }
        }

        if (FUSED && i + 1 < NK) stageA_f(i + 1);
        __syncthreads();
    }

    // epilogue: bias + store (half2 or float2)
    #pragma unroll
    for (int mt = 0; mt < 4; mt++) {
        const int r = bm + wm * 64 + mt * 16 + g;
        #pragma unroll
        for (int nt = 0; nt < 4; nt++) {
            const int cl = wn * 32 + nt * 8 + 2 * t;
            const int col = bnG + cl;
            const float bx = BI[bn + cl], by = BI[bn + cl + 1];
            if (OUTF32) {
                float* Cf = (float*)P.C;
                *(float2*)(Cf + (size_t)r * P.ldc + col) =
                    make_float2(acc[mt][nt][0] + bx, acc[mt][nt][1] + by);
                *(float2*)(Cf + (size_t)(r + 8) * P.ldc + col) =
                    make_float2(acc[mt][nt][2] + bx, acc[mt][nt][3] + by);
            } else {
                __half* Ch = (__half*)P.C;
                *(uint32_t*)(Ch + (size_t)r * P.ldc + col) =
                    packh2(acc[mt][nt][0] + bx, acc[mt][nt][1] + by);
                *(uint32_t*)(Ch + (size_t)(r + 8) * P.ldc + col) =
                    packh2(acc[mt][nt][2] + bx, acc[mt][nt][3] + by);
            }
        }
    }
}

// ---------------------------------------------------------------------------
// FP16 flash attention, HD=64, BQ=128, BK=64, 8 warps.
// Q frags in regs (ldmatrix once); K ldmatrix; V ldmatrix.trans;
// P = QK^T accumulator converted in-register (fragment layouts coincide).
// cp.async double-buffered K/V. Grid: (L/128, NH, z=(combo,batch)).
// ---------------------------------------------------------------------------
struct FlashP {
    const __half *Qp[4], *Kp[4], *Vp[4]; __half* Op[4];
    int sq, skv, so, cmask, cshift;
};

__global__ __launch_bounds__(256, 2) void flash_k(FlashP P)
{
    extern __shared__ char fsm[];
    const uint32_t smb = (uint32_t)__cvta_generic_to_shared(fsm);
    // Q @0 (16KB), K[s] @16K + s*8K, V[s] @32K + s*8K

    const int z = blockIdx.z;
    const int c = z & P.cmask;
    const int b = z >> P.cshift;
    const int q0 = blockIdx.x * 128;
    const int h  = blockIdx.y;

    const int tid = threadIdx.x;
    const int w = tid >> 5;
    const int lane = tid & 31;
    const int g = lane >> 2;
    const int t = lane & 3;
    const int lr = lane & 15;
    const int lh = lane >> 4;

    const __half* Qb = P.Qp[c] + (size_t)b * SEQL * P.sq  + (size_t)h * 64;
    const __half* Kb = P.Kp[c] + (size_t)b * SEQL * P.skv + (size_t)h * 64;
    const __half* Vb = P.Vp[c] + (size_t)b * SEQL * P.skv + (size_t)h * 64;
    __half*       Ob = P.Op[c] + (size_t)b * SEQL * P.so  + (size_t)h * 64;

    // stage Q (128x64 half)
    {
        const int sr = tid >> 1;
        const int sc = (tid & 1) * 4;
        const __half* src = Qb + (size_t)(q0 + sr) * P.sq + sc * 8;
        #pragma unroll
        for (int cc = 0; cc < 4; cc++)
            cp16(smb + swz(sr, sc + cc), src + cc * 8);
        cpcommit();
    }

    const int kr = tid >> 2;        // 0..63
    const int kc = (tid & 3) * 2;   // chunks {0,2,4,6}
    auto stageKV = [&](int kt, int s) {
        const __half* pk = Kb + (size_t)(kt + kr) * P.skv + kc * 8;
        const __half* pv = Vb + (size_t)(kt + kr) * P.skv + kc * 8;
        const uint32_t kbase = smb + 16384u + (uint32_t)s * 8192u;
        const uint32_t vbase = smb + 32768u + (uint32_t)s * 8192u;
        cp16(kbase + swz(kr, kc),     pk);
        cp16(kbase + swz(kr, kc + 1), pk + 8);
        cp16(vbase + swz(kr, kc),     pv);
        cp16(vbase + swz(kr, kc + 1), pv + 8);
    };

    stageKV(0, 0);  cpcommit();
    stageKV(64, 1); cpcommit();
    cpwait<1>();    // Q + KV0 complete
    __syncthreads();

    // Q fragments (warp w owns q rows 16w..16w+15)
    uint32_t qa[4][4];
    #pragma unroll
    for (int kb = 0; kb < 4; kb++)
        ldsm4(qa[kb][0], qa[kb][1], qa[kb][2], qa[kb][3],
              smb + swz(w * 16 + lr, kb * 2 + lh));

    const float qsc = 0.125f * 1.4426950408889634f;  // (1/sqrt(64))*log2(e)

    float oacc[8][4] = {};
    float mi0 = -INFINITY, mi1 = -INFINITY;
    float li0 = 0.f, li1 = 0.f;

    const int NT = SEQL / 64;
    for (int it = 0; it < NT; it++) {
        const int s = it & 1;
        const uint32_t Kbase = smb + 16384u + (uint32_t)s * 8192u;
        const uint32_t Vbase = smb + 32768u + (uint32_t)s * 8192u;

        // S = Q @ K^T
        float sacc[8][4] = {};
        #pragma unroll
        for (int kb = 0; kb < 4; kb++) {
            #pragma unroll
            for (int np = 0; np < 4; np++) {
                uint32_t k0, k1, k2, k3;
                ldsm4(k0, k1, k2, k3, Kbase + swz(np * 16 + lr, kb * 2 + lh));
                mma_f16(sacc[2*np][0], sacc[2*np][1], sacc[2*np][2], sacc[2*np][3],
                        qa[kb][0], qa[kb][1], qa[kb][2], qa[kb][3], k0, k2);
                mma_f16(sacc[2*np+1][0], sacc[2*np+1][1], sacc[2*np+1][2], sacc[2*np+1][3],
                        qa[kb][0], qa[kb][1], qa[kb][2], qa[kb][3], k1, k3);
            }
        }

        // online softmax (exp2 domain, scale applied here)
        uint32_t pa[4][4];
        {
            float sc_[8][4];
            float mx0 = -INFINITY, mx1 = -INFINITY;
            #pragma unroll
            for (int nt = 0; nt < 8; nt++) {
                sc_[nt][0] = sacc[nt][0] * qsc; sc_[nt][1] = sacc[nt][1] * qsc;
                sc_[nt][2] = sacc[nt][2] * qsc; sc_[nt][3] = sacc[nt][3] * qsc;
                mx0 = fmaxf(mx0, fmaxf(sc_[nt][0], sc_[nt][1]));
                mx1 = fmaxf(mx1, fmaxf(sc_[nt][2], sc_[nt][3]));
            }
            mx0 = fmaxf(mx0, __shfl_xor_sync(0xffffffffu, mx0, 1, 4));
            mx0 = fmaxf(mx0, __shfl_xor_sync(0xffffffffu, mx0, 2, 4));
            mx1 = fmaxf(mx1, __shfl_xor_sync(0xffffffffu, mx1, 1, 4));
            mx1 = fmaxf(mx1, __shfl_xor_sync(0xffffffffu, mx1, 2, 4));
            const float mn0 = fmaxf(mi0, mx0);
            const float mn1 = fmaxf(mi1, mx1);
            const float c0 = exp2f(mi0 - mn0);
            const float c1 = exp2f(mi1 - mn1);
            mi0 = mn0; mi1 = mn1;

            float rs0 = 0.f, rs1 = 0.f;
            #pragma unroll
            for (int nt = 0; nt < 8; nt++) {
                sc_[nt][0] = exp2f(sc_[nt][0] - mn0);
                sc_[nt][1] = exp2f(sc_[nt][1] - mn0);
                sc_[nt][2] = exp2f(sc_[nt][2] - mn1);
                sc_[nt][3] = exp2f(sc_[nt][3] - mn1);
            }
            // pack P fragments (QK^T C-frag == PV A-frag) and sum rounded values
            #pragma unroll
            for (int kb = 0; kb < 4; kb++) {
                __half2 h0 = __floats2half2_rn(sc_[2*kb][0],   sc_[2*kb][1]);
                __half2 h1 = __floats2half2_rn(sc_[2*kb][2],   sc_[2*kb][3]);
                __half2 h2 = __floats2half2_rn(sc_[2*kb+1][0], sc_[2*kb+1][1]);
                __half2 h3 = __floats2half2_rn(sc_[2*kb+1][2], sc_[2*kb+1][3]);
                pa[kb][0] = *(uint32_t*)&h0;
                pa[kb][1] = *(uint32_t*)&h1;
                pa[kb][2] = *(uint32_t*)&h2;
                pa[kb][3] = *(uint32_t*)&h3;
                float2 f0 = __half22float2(h0), f1 = __half22float2(h1);
                float2 f2 = __half22float2(h2), f3 = __half22float2(h3);
                rs0 += f0.x + f0.y + f2.x + f2.y;
                rs1 += f1.x + f1.y + f3.x + f3.y;
            }
            rs0 += __shfl_xor_sync(0xffffffffu, rs0, 1, 4);
            rs0 += __shfl_xor_sync(0xffffffffu, rs0, 2, 4);
            rs1 += __shfl_xor_sync(0xffffffffu, rs1, 1, 4);
            rs1 += __shfl_xor_sync(0xffffffffu, rs1, 2, 4);
            li0 = li0 * c0 + rs0;
            li1 = li1 * c1 + rs1;
            #pragma unroll
            for (int nt = 0; nt < 8; nt++) {
                oacc[nt][0] *= c0; oacc[nt][1] *= c0;
                oacc[nt][2] *= c1; oacc[nt][3] *= c1;
            }
        }

        // O += P @ V (V^T fragments via ldmatrix.trans)
        #pragma unroll
        for (int kb = 0; kb < 4; kb++) {
            #pragma unroll
            for (int np = 0; np < 4; np++) {
                uint32_t v0, v1, v2, v3;
                ldsm4t(v0, v1, v2, v3, Vbase + swz(kb * 16 + lr, np * 2 + lh));
                mma_f16(oacc[2*np][0], oacc[2*np][1], oacc[2*np][2], oacc[2*np][3],
                        pa[kb][0], pa[kb][1], pa[kb][2], pa[kb][3], v0, v1);
                mma_f16(oacc[2*np+1][0], oacc[2*np+1][1], oacc[2*np+1][2], oacc[2*np+1][3],
                        pa[kb][0], pa[kb][1], pa[kb][2], pa[kb][3], v2, v3);
            }
        }

        __syncthreads();   // all warps done reading buffer s
        if (it + 2 < NT) { stageKV((it + 2) * 64, s); cpcommit(); }
        if (it + 1 < NT) { cpwait<1>(); __syncthreads(); }
    }

    // epilogue
    {
        const float inv0 = 1.0f / li0;
        const float inv1 = 1.0f / li1;
        const int r0 = q0 + 16 * w + g;
        #pragma unroll
        for (int nt = 0; nt < 8; nt++) {
            const int col = nt * 8 + 2 * t;
            *(uint32_t*)(Ob + (size_t)r0 * P.so + col) =
                packh2(oacc[nt][0] * inv0, oacc[nt][1] * inv0);
            *(uint32_t*)(Ob + (size_t)(r0 + 8) * P.so + col) =
                packh2(oacc[nt][2] * inv1, oacc[nt][3] * inv1);
        }
    }
}

// ---------------------------------------------------------------------------
extern "C" void kernel_launch(void* const* d_in, const int* in_sizes, int n_in,
                              void* d_out, int out_size)
{
    (void)in_sizes; (void)n_in; (void)out_size;

    const float* hs        = (const float*)d_in[0];
    const float* txt       = (const float*)d_in[1];
    const float* w_q_img   = (const float*)d_in[2];
    const float* b_q_img   = (const float*)d_in[3];
    const float* w_k_img   = (const float*)d_in[4];
    const float* b_k_img   = (const float*)d_in[5];
    const float* w_v_img   = (const float*)d_in[6];
    const float* b_v_img   = (const float*)d_in[7];
    const float* w_q_txt   = (const float*)d_in[8];
    const float* b_q_txt   = (const float*)d_in[9];
    const float* w_k_txt   = (const float*)d_in[10];
    const float* b_k_txt   = (const float*)d_in[11];
    const float* w_v_txt   = (const float*)d_in[12];
    const float* b_v_txt   = (const float*)d_in[13];
    const float* w_out_img = (const float*)d_in[14];
    const float* b_out_img = (const float*)d_in[15];
    const float* w_out_txt = (const float*)d_in[16];
    const float* b_out_txt = (const float*)d_in[17];
    const float* w_cat     = (const float*)d_in[18];
    const float* b_cat     = (const float*)d_in[19];
    const float* in_proj_w = (const float*)d_in[20];
    const float* in_proj_b = (const float*)d_in[21];
    const float* out_proj_w= (const float*)d_in[22];
    const float* out_proj_b= (const float*)d_in[23];
    float* out = (float*)d_out;

    constexpr size_t U  = (size_t)MTOT * HDIM;   // 4,194,304 halves
    constexpr size_t QW = (size_t)512 * 512;
    __half* S;
    cudaGetSymbolAddress((void**)&S, g_scratch);

    __half* HSh    = S;
    __half* TXTh   = S + U;
    __half* QKV0h  = S + 2 * U;
    __half* QKV1h  = S + 5 * U;
    __half* C0     = S + 8 * U;
    __half* C1     = S + 9 * U;
    __half* C2     = S + 10 * U;
    __half* C3     = S + 11 * U;
    __half* OUTCATh= S + 12 * U;
    __half* OUTBh  = S + 14 * U;
    __half* QKV2h  = S + 15 * U;
    __half* CTXh   = S + 18 * U;
    __half* WB     = S + 19 * U;
    __half* whqi = WB;           __half* whki = WB + QW;     __half* whvi = WB + 2 * QW;
    __half* whqt = WB + 3 * QW;  __half* whkt = WB + 4 * QW; __half* whvt = WB + 5 * QW;
    __half* whoi = WB + 6 * QW;  __half* whot = WB + 7 * QW; __half* whop = WB + 8 * QW;
    __half* whcat = WB + 9 * QW;            // 512*1024
    __half* whinp = whcat + 512 * 1024;     // 1536*512

    const int GSM = 65536, FSM = 49152;
    cudaFuncSetAttribute(gemm_k<false,false>, cudaFuncAttributeMaxDynamicSharedMemorySize, GSM);
    cudaFuncSetAttribute(gemm_k<true,false>,  cudaFuncAttributeMaxDynamicSharedMemorySize, GSM);
    cudaFuncSetAttribute(gemm_k<false,true>,  cudaFuncAttributeMaxDynamicSharedMemorySize, GSM);
    cudaFuncSetAttribute(flash_k,             cudaFuncAttributeMaxDynamicSharedMemorySize, FSM);

    // 0) fp32 -> fp16 conversions
    {
        CvtP p;
        const float* srcs[13] = {hs, txt, w_q_img, w_k_img, w_v_img, w_q_txt, w_k_txt,
                                 w_v_txt, w_out_img, w_out_txt, out_proj_w, w_cat, in_proj_w};
        __half* dsts[13] = {HSh, TXTh, whqi, whki, whvi, whqt, whkt,
                            whvt, whoi, whot, whop, whcat, whinp};
        int ns[13] = {(int)U, (int)U, (int)QW, (int)QW, (int)QW, (int)QW, (int)QW,
                      (int)QW, (int)QW, (int)QW, (int)QW, 512*1024, 1536*512};
        int tot = 0;
        for (int i = 0; i < 13; i++) { p.src[i]=srcs[i]; p.dst[i]=dsts[i]; p.nblk[i]=ns[i]/1024; tot+=ns[i]/1024; }
        cvt_k<<<tot, 256>>>(p);
    }

    const dim3 blk(256);
    const dim3 g512(4, 64);
    const dim3 g1536(12, 64);

    // 1,2) merged QKV projections -> interleaved half [8192 x 1536]
    {
        GemmP p{HSh, nullptr, HDIM, whqi, whki, whvi, b_q_img, b_k_img, b_v_img,
                QKV0h, 3 * HDIM, HDIM};
        gemm_k<false,false><<<g1536, blk, GSM>>>(p);
        GemmP q{TXTh, nullptr, HDIM, whqt, whkt, whvt, b_q_txt, b_k_txt, b_v_txt,
                QKV1h, 3 * HDIM, HDIM};
        gemm_k<false,false><<<g1536, blk, GSM>>>(q);
    }

    // 3) four attentions in one launch
    {
        FlashP p;
        p.Qp[0] = QKV0h; p.Kp[0] = QKV0h + HDIM; p.Vp[0] = QKV0h + 2 * HDIM; p.Op[0] = C0;
        p.Qp[1] = QKV1h; p.Kp[1] = QKV1h + HDIM; p.Vp[1] = QKV1h + 2 * HDIM; p.Op[1] = C1;
        p.Qp[2] = QKV0h; p.Kp[2] = QKV1h + HDIM; p.Vp[2] = QKV1h + 2 * HDIM; p.Op[2] = C2;
        p.Qp[3] = QKV1h; p.Kp[3] = QKV0h + HDIM; p.Vp[3] = QKV0h + 2 * HDIM; p.Op[3] = C3;
        p.sq = 3 * HDIM; p.skv = 3 * HDIM; p.so = HDIM; p.cmask = 3; p.cshift = 2;
        flash_k<<<dim3(SEQL / 128, 8, BATCH * 4), blk, FSM>>>(p);
    }

    // 4,5) out_img / out_txt fused (a+b)*0.5 -> concat halves
    {
        GemmP p{C0, C2, HDIM, whoi, nullptr, nullptr, b_out_img, nullptr, nullptr,
                OUTCATh, 2 * HDIM, HDIM};
        gemm_k<true,false><<<g512, blk, GSM>>>(p);
        GemmP q{C1, C3, HDIM, whot, nullptr, nullptr, b_out_txt, nullptr, nullptr,
                OUTCATh + HDIM, 2 * HDIM, HDIM};
        gemm_k<true,false><<<g512, blk, GSM>>>(q);
    }

    // 6) cat linear (K=1024)
    {
        GemmP p{OUTCATh, nullptr, 2 * HDIM, whcat, nullptr, nullptr, b_cat, nullptr, nullptr,
                OUTBh, HDIM, 2 * HDIM};
        gemm_k<false,false><<<g512, blk, GSM>>>(p);
    }

    // 7) pooling in_proj
    {
        GemmP p{OUTBh, nullptr, HDIM,
                whinp, whinp + 512 * 512, whinp + 1024 * 512,
                in_proj_b, in_proj_b + 512, in_proj_b + 1024,
                QKV2h, 3 * HDIM, HDIM};
        gemm_k<false,false><<<g1536, blk, GSM>>>(p);
    }

    // 8) pooling self-attention
    {
        FlashP p;
        p.Qp[0] = QKV2h; p.Kp[0] = QKV2h + HDIM; p.Vp[0] = QKV2h + 2 * HDIM; p.Op[0] = CTXh;
        p.Qp[1] = p.Qp[2] = p.Qp[3] = QKV2h;
        p.Kp[1] = p.Kp[2] = p.Kp[3] = QKV2h + HDIM;
        p.Vp[1] = p.Vp[2] = p.Vp[3] = QKV2h + 2 * HDIM;
        p.Op[1] = p.Op[2] = p.Op[3] = CTXh;
        p.sq = 3 * HDIM; p.skv = 3 * HDIM; p.so = HDIM; p.cmask = 0; p.cshift = 0;
        flash_k<<<dim3(SEQL / 128, 8, BATCH), blk, FSM>>>(p);
    }

    // 9) out_proj -> fp32 output
    {
        GemmP p{CTXh, nullptr, HDIM, whop, nullptr, nullptr, out_proj_b, nullptr, nullptr,
                out, HDIM, HDIM};
        gemm_k<false,true><<<g512, blk, GSM>>>(p);
    }
}

// round 6
// speedup vs baseline: 7.1206x; 1.0226x over previous
#include <cuda_runtime.h>
#include <cuda_fp16.h>
#include <math.h>
#include <stdint.h>

#define HDIM 512
#define BATCH 8
#define SEQL 1024
#define MTOT 8192

// half scratch: 84M halves = 168MB
__device__ __half g_scratch[(size_t)84 * 1024 * 1024];

// ---------------------------------------------------------------------------
// Primitives
// ---------------------------------------------------------------------------
__device__ __forceinline__ void mma_f16(float& d0, float& d1, float& d2, float& d3,
                                        uint32_t a0, uint32_t a1, uint32_t a2, uint32_t a3,
                                        uint32_t b0, uint32_t b1)
{
    asm volatile(
        "mma.sync.aligned.m16n8k16.row.col.f32.f16.f16.f32 "
        "{%0,%1,%2,%3}, {%4,%5,%6,%7}, {%8,%9}, {%0,%1,%2,%3};"
        : "+f"(d0), "+f"(d1), "+f"(d2), "+f"(d3)
        : "r"(a0), "r"(a1), "r"(a2), "r"(a3), "r"(b0), "r"(b1));
}

__device__ __forceinline__ void ldsm4(uint32_t& r0, uint32_t& r1, uint32_t& r2, uint32_t& r3,
                                      uint32_t addr)
{
    asm volatile("ldmatrix.sync.aligned.m8n8.x4.shared.b16 {%0,%1,%2,%3}, [%4];"
                 : "=r"(r0), "=r"(r1), "=r"(r2), "=r"(r3) : "r"(addr));
}
__device__ __forceinline__ void ldsm4t(uint32_t& r0, uint32_t& r1, uint32_t& r2, uint32_t& r3,
                                       uint32_t addr)
{
    asm volatile("ldmatrix.sync.aligned.m8n8.x4.trans.shared.b16 {%0,%1,%2,%3}, [%4];"
                 : "=r"(r0), "=r"(r1), "=r"(r2), "=r"(r3) : "r"(addr));
}

__device__ __forceinline__ void cp16(uint32_t dst, const void* src) {
    asm volatile("cp.async.cg.shared.global [%0], [%1], 16;" :: "r"(dst), "l"(src));
}
__device__ __forceinline__ void cpcommit() { asm volatile("cp.async.commit_group;"); }
template<int N> __device__ __forceinline__ void cpwait() {
    asm volatile("cp.async.wait_group %0;" :: "n"(N));
}

// XOR swizzle: rows of 128B (64 halves), 16B chunk c in 0..7
__device__ __forceinline__ uint32_t swz(uint32_t r, uint32_t c) {
    return r * 128u + ((c ^ (r & 7u)) << 4);
}

__device__ __forceinline__ uint32_t packh2(float x, float y) {
    __half2 h = __floats2half2_rn(x, y);
    return *(uint32_t*)&h;
}

// ---------------------------------------------------------------------------
// fp32 -> fp16 conversion kernel
// ---------------------------------------------------------------------------
struct CvtP { const float* src[13]; __half* dst[13]; int nblk[13]; };

__global__ __launch_bounds__(256) void cvt_k(CvtP P)
{
    int b = blockIdx.x;
    int s = 0;
    while (b >= P.nblk[s]) { b -= P.nblk[s]; ++s; }
    size_t i = ((size_t)b * 256 + threadIdx.x) * 4;
    float4 v = *(const float4*)(P.src[s] + i);
    uint2 o;
    o.x = packh2(v.x, v.y);
    o.y = packh2(v.z, v.w);
    *(uint2*)(P.dst[s] + i) = o;
}

// ---------------------------------------------------------------------------
// FP16 GEMM (NT): C = (A or 0.5*(A1+A2)) @ W^T + bias, times per-seg osc.
// CTA 128x128, BK=64, 256 thr (8 warps 2x4, warp tile 64x32).
// 3-stage cp.async pipeline (96KB smem), single sync/iter, XOR swizzle.
// Per-512-col segment: A1/A2/W/Bi/Ch/osc arrays.
// ---------------------------------------------------------------------------
struct GemmP {
    const __half* A1[3]; const __half* A2[3];
    const __half* W[3];  const float*  Bi[3];
    __half* Ch[3]; float* Cf;
    float osc[3];
    int lda, ldc, K;
};

template<bool FUSED, bool OUTF32>
__global__ __launch_bounds__(256, 2) void gemm_k(GemmP P)
{
    extern __shared__ char sm[];
    const uint32_t smb = (uint32_t)__cvta_generic_to_shared(sm);
    // stage s: A @ s*32768, W @ s*32768 + 16384  (3 stages, 96KB)

    const int bm  = blockIdx.y * 128;
    const int bnG = blockIdx.x * 128;
    const int seg = bnG >> 9;
    const int bn  = bnG & 511;
    const __half* A1 = P.A1[seg];
    const __half* A2 = P.A2[seg];
    const __half* W  = P.W[seg];
    const float*  BI = P.Bi[seg];
    const float  osc = P.osc[seg];

    const int tid  = threadIdx.x;
    const int warp = tid >> 5;
    const int lane = tid & 31;
    const int g = lane >> 2;
    const int t = lane & 3;
    const int wm = warp >> 2;
    const int wn = warp & 3;
    const int lr = lane & 15;
    const int lh = lane >> 4;

    const int sr = tid >> 1;        // staging row 0..127
    const int sc = (tid & 1) * 4;   // staging chunk base

    // hoisted ldmatrix address pieces
    const uint32_t lrow128 = (uint32_t)lr * 128u;
    uint32_t x4[4];
    #pragma unroll
    for (int kb = 0; kb < 4; kb++)
        x4[kb] = (uint32_t)(((kb * 2 + lh) ^ (lr & 7)) << 4);

    const int NK = P.K >> 6;
    float acc[4][4][4] = {};

    auto issueW = [&](int i) {
        const uint32_t dst = smb + (uint32_t)(i % 3) * 32768u + 16384u;
        const __half* src = W + (size_t)(bn + sr) * P.K + i * 64 + sc * 8;
        #pragma unroll
        for (int c = 0; c < 4; c++)
            cp16(dst + swz(sr, sc + c), src + c * 8);
    };
    auto issueA = [&](int i) {
        const uint32_t dst = smb + (uint32_t)(i % 3) * 32768u;
        const __half* src = A1 + (size_t)(bm + sr) * P.lda + i * 64 + sc * 8;
        #pragma unroll
        for (int c = 0; c < 4; c++)
            cp16(dst + swz(sr, sc + c), src + c * 8);
    };
    auto stageA_f = [&](int i) {   // (A1+A2)*0.5, STS half
        char* dstb = sm + (size_t)(i % 3) * 32768u;
        const __half* p1 = A1 + (size_t)(bm + sr) * P.lda + i * 64 + sc * 8;
        const __half* p2 = A2 + (size_t)(bm + sr) * P.lda + i * 64 + sc * 8;
        const __half2 hf = __float2half2_rn(0.5f);
        #pragma unroll
        for (int c = 0; c < 4; c++) {
            float4 x = *(const float4*)(p1 + c * 8);
            float4 y = *(const float4*)(p2 + c * 8);
            const __half2* xh = (const __half2*)&x;
            const __half2* yh = (const __half2*)&y;
            __half2 z[4];
            #pragma unroll
            for (int j = 0; j < 4; j++)
                z[j] = __hmul2(__hadd2(xh[j], yh[j]), hf);
            *(float4*)(dstb + swz(sr, sc + c)) = *(float4*)z;
        }
    };
    auto stage = [&](int i) {
        if (FUSED) { stageA_f(i); issueW(i); }
        else       { issueA(i);   issueW(i); }
        cpcommit();
    };

    // prologue: 2 stages in flight
    stage(0);
    if (NK > 1) stage(1);

    for (int i = 0; i < NK; i++) {
        if (i + 1 < NK) cpwait<1>(); else cpwait<0>();
        __syncthreads();

        const uint32_t Ab = smb + (uint32_t)(i % 3) * 32768u;
        const uint32_t Wb = Ab + 16384u;

        #pragma unroll
        for (int kb = 0; kb < 4; kb++) {
            uint32_t bw[2][4];
            #pragma unroll
            for (int np = 0; np < 2; np++)
                ldsm4(bw[np][0], bw[np][1], bw[np][2], bw[np][3],
                      Wb + (uint32_t)(wn * 32 + np * 16) * 128u + lrow128 + x4[kb]);
            #pragma unroll
            for (int mt = 0; mt < 4; mt++) {
                uint32_t a0, a1, a2, a3;
                ldsm4(a0, a1, a2, a3,
                      Ab + (uint32_t)(wm * 64 + mt * 16) * 128u + lrow128 + x4[kb]);
                #pragma unroll
                for (int nt = 0; nt < 4; nt++) {
                    const int np = nt >> 1, hi = nt & 1;
                    mma_f16(acc[mt][nt][0], acc[mt][nt][1], acc[mt][nt][2], acc[mt][nt][3],
                            a0, a1, a2, a3,
                            bw[np][hi ? 1 : 0], bw[np][hi ? 3 : 2]);
                }
            }
        }

        if (i + 2 < NK) stage(i + 2);
    }

    // epilogue: (acc + bias) * osc
    #pragma unroll
    for (int mt = 0; mt < 4; mt++) {
        const int r = bm + wm * 64 + mt * 16 + g;
        #pragma unroll
        for (int nt = 0; nt < 4; nt++) {
            const int cl = bn + wn * 32 + nt * 8 + 2 * t;
            const float bx = BI[cl], by = BI[cl + 1];
            if (OUTF32) {
                float* Cf = P.Cf;
                *(float2*)(Cf + (size_t)r * P.ldc + cl) =
                    make_float2((acc[mt][nt][0] + bx) * osc, (acc[mt][nt][1] + by) * osc);
                *(float2*)(Cf + (size_t)(r + 8) * P.ldc + cl) =
                    make_float2((acc[mt][nt][2] + bx) * osc, (acc[mt][nt][3] + by) * osc);
            } else {
                __half* Ch = P.Ch[seg];
                *(uint32_t*)(Ch + (size_t)r * P.ldc + cl) =
                    packh2((acc[mt][nt][0] + bx) * osc, (acc[mt][nt][1] + by) * osc);
                *(uint32_t*)(Ch + (size_t)(r + 8) * P.ldc + cl) =
                    packh2((acc[mt][nt][2] + bx) * osc, (acc[mt][nt][3] + by) * osc);
            }
        }
    }
}

// ---------------------------------------------------------------------------
// FP16 flash attention, HD=64, BQ=128, BK=64, 8 warps.
// Q pre-scaled by (1/8)*log2(e) upstream (GEMM epilogue) -> S is log2-domain.
// 3-stage cp.async K/V pipeline, 1 sync/tile. P frag = S accumulator frag.
// Grid: (L/128, NH, z=(combo,batch)).
// ---------------------------------------------------------------------------
struct FlashP {
    const __half *Qp[4], *Kp[4], *Vp[4]; __half* Op[4];
    int sq, skv, so, cmask, cshift;
};

__global__ __launch_bounds__(256, 2) void flash_k(FlashP P)
{
    extern __shared__ char fsm[];
    const uint32_t smb = (uint32_t)__cvta_generic_to_shared(fsm);
    // Q @0 (16KB), K[s] @16384+s*8192 (3), V[s] @40960+s*8192 (3) = 64KB

    const int z = blockIdx.z;
    const int c = z & P.cmask;
    const int b = z >> P.cshift;
    const int q0 = blockIdx.x * 128;
    const int h  = blockIdx.y;

    const int tid = threadIdx.x;
    const int w = tid >> 5;
    const int lane = tid & 31;
    const int g = lane >> 2;
    const int t = lane & 3;
    const int lr = lane & 15;
    const int lh = lane >> 4;

    const __half* Qb = P.Qp[c] + (size_t)b * SEQL * P.sq  + (size_t)h * 64;
    const __half* Kb = P.Kp[c] + (size_t)b * SEQL * P.skv + (size_t)h * 64;
    const __half* Vb = P.Vp[c] + (size_t)b * SEQL * P.skv + (size_t)h * 64;
    __half*       Ob = P.Op[c] + (size_t)b * SEQL * P.so  + (size_t)h * 64;

    // hoisted ldmatrix address pieces
    const uint32_t lrow128 = (uint32_t)lr * 128u;
    uint32_t x4[4];
    #pragma unroll
    for (int kb = 0; kb < 4; kb++)
        x4[kb] = (uint32_t)(((kb * 2 + lh) ^ (lr & 7)) << 4);

    // stage Q (group 0)
    {
        const int sr = tid >> 1;
        const int sc = (tid & 1) * 4;
        const __half* src = Qb + (size_t)(q0 + sr) * P.sq + sc * 8;
        #pragma unroll
        for (int cc = 0; cc < 4; cc++)
            cp16(smb + swz(sr, sc + cc), src + cc * 8);
        cpcommit();
    }

    const int kr = tid >> 2;        // 0..63
    const int kc = (tid & 3) * 2;   // chunks {0,2,4,6}
    auto stageKV = [&](int kt, int s) {
        const __half* pk = Kb + (size_t)(kt + kr) * P.skv + kc * 8;
        const __half* pv = Vb + (size_t)(kt + kr) * P.skv + kc * 8;
        const uint32_t kbase = smb + 16384u + (uint32_t)s * 8192u;
        const uint32_t vbase = smb + 40960u + (uint32_t)s * 8192u;
        cp16(kbase + swz(kr, kc),     pk);
        cp16(kbase + swz(kr, kc + 1), pk + 8);
        cp16(vbase + swz(kr, kc),     pv);
        cp16(vbase + swz(kr, kc + 1), pv + 8);
        cpcommit();
    };

    stageKV(0, 0);
    stageKV(64, 1);
    cpwait<1>();    // Q + KV0 complete
    __syncthreads();

    // Q fragments (pre-scaled upstream)
    uint32_t qa[4][4];
    #pragma unroll
    for (int kb = 0; kb < 4; kb++)
        ldsm4(qa[kb][0], qa[kb][1], qa[kb][2], qa[kb][3],
              smb + (uint32_t)(w * 2048) + lrow128 + x4[kb]);

    float oacc[8][4] = {};
    float mi0 = -INFINITY, mi1 = -INFINITY;
    float li0 = 0.f, li1 = 0.f;

    const int NT = SEQL / 64;
    for (int it = 0; it < NT; it++) {
        const int s = it % 3;
        const uint32_t Kbase = smb + 16384u + (uint32_t)s * 8192u + lrow128;
        const uint32_t Vbase = smb + 40960u + (uint32_t)s * 8192u + lrow128;

        // S = Q @ K^T (already log2-domain via pre-scaled Q)
        float sacc[8][4] = {};
        #pragma unroll
        for (int kb = 0; kb < 4; kb++) {
            #pragma unroll
            for (int np = 0; np < 4; np++) {
                uint32_t k0, k1, k2, k3;
                ldsm4(k0, k1, k2, k3, Kbase + (uint32_t)(np * 2048) + x4[kb]);
                mma_f16(sacc[2*np][0], sacc[2*np][1], sacc[2*np][2], sacc[2*np][3],
                        qa[kb][0], qa[kb][1], qa[kb][2], qa[kb][3], k0, k2);
                mma_f16(sacc[2*np+1][0], sacc[2*np+1][1], sacc[2*np+1][2], sacc[2*np+1][3],
                        qa[kb][0], qa[kb][1], qa[kb][2], qa[kb][3], k1, k3);
            }
        }

        // online softmax (exp2 domain)
        uint32_t pa[4][4];
        {
            float mx0 = -INFINITY, mx1 = -INFINITY;
            #pragma unroll
            for (int nt = 0; nt < 8; nt++) {
                mx0 = fmaxf(mx0, fmaxf(sacc[nt][0], sacc[nt][1]));
                mx1 = fmaxf(mx1, fmaxf(sacc[nt][2], sacc[nt][3]));
            }
            mx0 = fmaxf(mx0, __shfl_xor_sync(0xffffffffu, mx0, 1, 4));
            mx0 = fmaxf(mx0, __shfl_xor_sync(0xffffffffu, mx0, 2, 4));
            mx1 = fmaxf(mx1, __shfl_xor_sync(0xffffffffu, mx1, 1, 4));
            mx1 = fmaxf(mx1, __shfl_xor_sync(0xffffffffu, mx1, 2, 4));
            const float mn0 = fmaxf(mi0, mx0);
            const float mn1 = fmaxf(mi1, mx1);
            const float c0 = exp2f(mi0 - mn0);
            const float c1 = exp2f(mi1 - mn1);
            mi0 = mn0; mi1 = mn1;

            float rs0 = 0.f, rs1 = 0.f;
            #pragma unroll
            for (int nt = 0; nt < 8; nt++) {
                sacc[nt][0] = exp2f(sacc[nt][0] - mn0);
                sacc[nt][1] = exp2f(sacc[nt][1] - mn0);
                sacc[nt][2] = exp2f(sacc[nt][2] - mn1);
                sacc[nt][3] = exp2f(sacc[nt][3] - mn1);
                rs0 += sacc[nt][0] + sacc[nt][1];
                rs1 += sacc[nt][2] + sacc[nt][3];
            }
            // pack P fragments (S C-frag == PV A-frag)
            #pragma unroll
            for (int kb = 0; kb < 4; kb++) {
                pa[kb][0] = packh2(sacc[2*kb][0],   sacc[2*kb][1]);
                pa[kb][1] = packh2(sacc[2*kb][2],   sacc[2*kb][3]);
                pa[kb][2] = packh2(sacc[2*kb+1][0], sacc[2*kb+1][1]);
                pa[kb][3] = packh2(sacc[2*kb+1][2], sacc[2*kb+1][3]);
            }
            rs0 += __shfl_xor_sync(0xffffffffu, rs0, 1, 4);
            rs0 += __shfl_xor_sync(0xffffffffu, rs0, 2, 4);
            rs1 += __shfl_xor_sync(0xffffffffu, rs1, 1, 4);
            rs1 += __shfl_xor_sync(0xffffffffu, rs1, 2, 4);
            li0 = li0 * c0 + rs0;
            li1 = li1 * c1 + rs1;

            const bool skip = __all_sync(0xffffffffu, (c0 == 1.0f) & (c1 == 1.0f));
            if (!skip) {
                #pragma unroll
                for (int nt = 0; nt < 8; nt++) {
                    oacc[nt][0] *= c0; oacc[nt][1] *= c0;
                    oacc[nt][2] *= c1; oacc[nt][3] *= c1;
                }
            }
        }

        // O += P @ V (V^T fragments via ldmatrix.trans)
        #pragma unroll
        for (int kb = 0; kb < 4; kb++) {
            #pragma unroll
            for (int np = 0; np < 4; np++) {
                uint32_t v0, v1, v2, v3;
                ldsm4t(v0, v1, v2, v3, Vbase + (uint32_t)(kb * 2048) + x4[np]);
                mma_f16(oacc[2*np][0], oacc[2*np][1], oacc[2*np][2], oacc[2*np][3],
                        pa[kb][0], pa[kb][1], pa[kb][2], pa[kb][3], v0, v1);
                mma_f16(oacc[2*np+1][0], oacc[2*np+1][1], oacc[2*np+1][2], oacc[2*np+1][3],
                        pa[kb][0], pa[kb][1], pa[kb][2], pa[kb][3], v2, v3);
            }
        }

        if (it + 1 < NT) {
            if (it + 2 < NT) { stageKV((it + 2) * 64, (it + 2) % 3); cpwait<1>(); }
            else             { cpwait<0>(); }
            __syncthreads();
        }
    }

    // epilogue
    {
        const float inv0 = 1.0f / li0;
        const float inv1 = 1.0f / li1;
        const int r0 = q0 + 16 * w + g;
        #pragma unroll
        for (int nt = 0; nt < 8; nt++) {
            const int col = nt * 8 + 2 * t;
            *(uint32_t*)(Ob + (size_t)r0 * P.so + col) =
                packh2(oacc[nt][0] * inv0, oacc[nt][1] * inv0);
            *(uint32_t*)(Ob + (size_t)(r0 + 8) * P.so + col) =
                packh2(oacc[nt][2] * inv1, oacc[nt][3] * inv1);
        }
    }
}

// ---------------------------------------------------------------------------
extern "C" void kernel_launch(void* const* d_in, const int* in_sizes, int n_in,
                              void* d_out, int out_size)
{
    (void)in_sizes; (void)n_in; (void)out_size;

    const float* hs        = (const float*)d_in[0];
    const float* txt       = (const float*)d_in[1];
    const float* w_q_img   = (const float*)d_in[2];
    const float* b_q_img   = (const float*)d_in[3];
    const float* w_k_img   = (const float*)d_in[4];
    const float* b_k_img   = (const float*)d_in[5];
    const float* w_v_img   = (const float*)d_in[6];
    const float* b_v_img   = (const float*)d_in[7];
    const float* w_q_txt   = (const float*)d_in[8];
    const float* b_q_txt   = (const float*)d_in[9];
    const float* w_k_txt   = (const float*)d_in[10];
    const float* b_k_txt   = (const float*)d_in[11];
    const float* w_v_txt   = (const float*)d_in[12];
    const float* b_v_txt   = (const float*)d_in[13];
    const float* w_out_img = (const float*)d_in[14];
    const float* b_out_img = (const float*)d_in[15];
    const float* w_out_txt = (const float*)d_in[16];
    const float* b_out_txt = (const float*)d_in[17];
    const float* w_cat     = (const float*)d_in[18];
    const float* b_cat     = (const float*)d_in[19];
    const float* in_proj_w = (const float*)d_in[20];
    const float* in_proj_b = (const float*)d_in[21];
    const float* out_proj_w= (const float*)d_in[22];
    const float* out_proj_b= (const float*)d_in[23];
    float* out = (float*)d_out;

    constexpr size_t U  = (size_t)MTOT * HDIM;
    constexpr size_t QW = (size_t)512 * 512;
    const float qsc = 0.125f * 1.4426950408889634f;  // (1/sqrt(64))*log2(e)

    __half* S;
    cudaGetSymbolAddress((void**)&S, g_scratch);

    __half* HSh    = S;
    __half* TXTh   = S + U;
    __half* QKV0h  = S + 2 * U;
    __half* QKV1h  = S + 5 * U;
    __half* C0     = S + 8 * U;
    __half* C1     = S + 9 * U;
    __half* C2     = S + 10 * U;
    __half* C3     = S + 11 * U;
    __half* OUTCATh= S + 12 * U;
    __half* OUTBh  = S + 14 * U;
    __half* QKV2h  = S + 15 * U;
    __half* CTXh   = S + 18 * U;
    __half* WB     = S + 19 * U;
    __half* whqi = WB;           __half* whki = WB + QW;     __half* whvi = WB + 2 * QW;
    __half* whqt = WB + 3 * QW;  __half* whkt = WB + 4 * QW; __half* whvt = WB + 5 * QW;
    __half* whoi = WB + 6 * QW;  __half* whot = WB + 7 * QW; __half* whop = WB + 8 * QW;
    __half* whcat = WB + 9 * QW;            // 512*1024
    __half* whinp = whcat + 512 * 1024;     // 1536*512

    const int GSM = 98304, FSM = 65536;
    cudaFuncSetAttribute(gemm_k<false,false>, cudaFuncAttributeMaxDynamicSharedMemorySize, GSM);
    cudaFuncSetAttribute(gemm_k<true,false>,  cudaFuncAttributeMaxDynamicSharedMemorySize, GSM);
    cudaFuncSetAttribute(gemm_k<false,true>,  cudaFuncAttributeMaxDynamicSharedMemorySize, GSM);
    cudaFuncSetAttribute(flash_k,             cudaFuncAttributeMaxDynamicSharedMemorySize, FSM);

    // 0) fp32 -> fp16 conversions
    {
        CvtP p;
        const float* srcs[13] = {hs, txt, w_q_img, w_k_img, w_v_img, w_q_txt, w_k_txt,
                                 w_v_txt, w_out_img, w_out_txt, out_proj_w, w_cat, in_proj_w};
        __half* dsts[13] = {HSh, TXTh, whqi, whki, whvi, whqt, whkt,
                            whvt, whoi, whot, whop, whcat, whinp};
        int ns[13] = {(int)U, (int)U, (int)QW, (int)QW, (int)QW, (int)QW, (int)QW,
                      (int)QW, (int)QW, (int)QW, (int)QW, 512*1024, 1536*512};
        int tot = 0;
        for (int i = 0; i < 13; i++) { p.src[i]=srcs[i]; p.dst[i]=dsts[i]; p.nblk[i]=ns[i]/1024; tot+=ns[i]/1024; }
        cvt_k<<<tot, 256>>>(p);
    }

    const dim3 blk(256);

    // 1,2) merged QKV projections -> interleaved half [8192 x 1536], Q pre-scaled
    {
        GemmP p = {};
        p.A1[0] = p.A1[1] = p.A1[2] = HSh;
        p.W[0] = whqi; p.W[1] = whki; p.W[2] = whvi;
        p.Bi[0] = b_q_img; p.Bi[1] = b_k_img; p.Bi[2] = b_v_img;
        p.Ch[0] = QKV0h; p.Ch[1] = QKV0h + 512; p.Ch[2] = QKV0h + 1024;
        p.osc[0] = qsc; p.osc[1] = 1.f; p.osc[2] = 1.f;
        p.lda = HDIM; p.ldc = 3 * HDIM; p.K = HDIM;
        gemm_k<false,false><<<dim3(12, 64), blk, GSM>>>(p);
        p.A1[0] = p.A1[1] = p.A1[2] = TXTh;
        p.W[0] = whqt; p.W[1] = whkt; p.W[2] = whvt;
        p.Bi[0] = b_q_txt; p.Bi[1] = b_k_txt; p.Bi[2] = b_v_txt;
        p.Ch[0] = QKV1h; p.Ch[1] = QKV1h + 512; p.Ch[2] = QKV1h + 1024;
        gemm_k<false,false><<<dim3(12, 64), blk, GSM>>>(p);
    }

    // 3) four attentions in one launch
    {
        FlashP p;
        p.Qp[0] = QKV0h; p.Kp[0] = QKV0h + 512; p.Vp[0] = QKV0h + 1024; p.Op[0] = C0;
        p.Qp[1] = QKV1h; p.Kp[1] = QKV1h + 512; p.Vp[1] = QKV1h + 1024; p.Op[1] = C1;
        p.Qp[2] = QKV0h; p.Kp[2] = QKV1h + 512; p.Vp[2] = QKV1h + 1024; p.Op[2] = C2;
        p.Qp[3] = QKV1h; p.Kp[3] = QKV0h + 512; p.Vp[3] = QKV0h + 1024; p.Op[3] = C3;
        p.sq = 3 * HDIM; p.skv = 3 * HDIM; p.so = HDIM; p.cmask = 3; p.cshift = 2;
        flash_k<<<dim3(SEQL / 128, 8, BATCH * 4), blk, FSM>>>(p);
    }

    // 4) merged out_img / out_txt: (a+b)*0.5 -> concat halves, one launch
    {
        GemmP p = {};
        p.A1[0] = C0; p.A2[0] = C2; p.A1[1] = C1; p.A2[1] = C3;
        p.W[0] = whoi; p.W[1] = whot;
        p.Bi[0] = b_out_img; p.Bi[1] = b_out_txt;
        p.Ch[0] = OUTCATh; p.Ch[1] = OUTCATh + 512;
        p.osc[0] = p.osc[1] = 1.f;
        p.lda = HDIM; p.ldc = 2 * HDIM; p.K = HDIM;
        gemm_k<true,false><<<dim3(8, 64), blk, GSM>>>(p);
    }

    // 5) cat linear (K=1024)
    {
        GemmP p = {};
        p.A1[0] = OUTCATh; p.W[0] = whcat; p.Bi[0] = b_cat;
        p.Ch[0] = OUTBh; p.osc[0] = 1.f;
        p.lda = 2 * HDIM; p.ldc = HDIM; p.K = 2 * HDIM;
        gemm_k<false,false><<<dim3(4, 64), blk, GSM>>>(p);
    }

    // 6) pooling in_proj, Q pre-scaled
    {
        GemmP p = {};
        p.A1[0] = p.A1[1] = p.A1[2] = OUTBh;
        p.W[0] = whinp; p.W[1] = whinp + 512 * 512; p.W[2] = whinp + 1024 * 512;
        p.Bi[0] = in_proj_b; p.Bi[1] = in_proj_b + 512; p.Bi[2] = in_proj_b + 1024;
        p.Ch[0] = QKV2h; p.Ch[1] = QKV2h + 512; p.Ch[2] = QKV2h + 1024;
        p.osc[0] = qsc; p.osc[1] = 1.f; p.osc[2] = 1.f;
        p.lda = HDIM; p.ldc = 3 * HDIM; p.K = HDIM;
        gemm_k<false,false><<<dim3(12, 64), blk, GSM>>>(p);
    }

    // 7) pooling self-attention
    {
        FlashP p;
        p.Qp[0] = QKV2h; p.Kp[0] = QKV2h + 512; p.Vp[0] = QKV2h + 1024; p.Op[0] = CTXh;
        p.Qp[1] = p.Qp[2] = p.Qp[3] = QKV2h;
        p.Kp[1] = p.Kp[2] = p.Kp[3] = QKV2h + 512;
        p.Vp[1] = p.Vp[2] = p.Vp[3] = QKV2h + 1024;
        p.Op[1] = p.Op[2] = p.Op[3] = CTXh;
        p.sq = 3 * HDIM; p.skv = 3 * HDIM; p.so = HDIM; p.cmask = 0; p.cshift = 0;
        flash_k<<<dim3(SEQL / 128, 8, BATCH), blk, FSM>>>(p);
    }

    // 8) out_proj -> fp32 output
    {
        GemmP p = {};
        p.A1[0] = CTXh; p.W[0] = whop; p.Bi[0] = out_proj_b;
        p.Cf = out; p.osc[0] = 1.f;
        p.lda = HDIM; p.ldc = HDIM; p.K = HDIM;
        gemm_k<false,true><<<dim3(4, 64), blk, GSM>>>(p);
    }
}